// round 3
// baseline (speedup 1.0000x reference)
#include <cuda_runtime.h>
#include <math.h>

// Problem constants
#define BB 4
#define TT 2048
#define HH 16
#define DD 64
#define NU 1024
#define MM (BB * TT)  // 8192

// Scratch (device globals: allocation-free)
__device__ float g_Q[(size_t)MM * NU];
__device__ float g_K[(size_t)MM * NU];
__device__ float g_V[(size_t)MM * NU];
__device__ float g_ctx[(size_t)MM * NU];

// ---------------------------------------------------------------------------
// GEMM (NT): C[m,n] = sum_k A[m,k] * W[n,k] + bias[n]
// A: (M,1024) row-major, W: (1024,1024) row-major (N x K)
// mode 0: C[m*1024 + n]
// mode 1: C[((b*16+h)*2048 + t)*64 + d]  (head-split layout), m=b*2048+t, n=h*64+d
// Tiling: 128x128x8, 256 threads, 8x8 microtile per thread.
// ---------------------------------------------------------------------------
__global__ __launch_bounds__(256) void gemm_nt(
    const float* __restrict__ A, const float* __restrict__ W,
    const float* __restrict__ bias, float* __restrict__ C, int mode)
{
    __shared__ float As[8][128];
    __shared__ float Bs[8][128];

    const int tid = threadIdx.x;
    const int tx = tid & 15;   // 0..15 column group
    const int ty = tid >> 4;   // 0..15 row group
    const int rowBase = blockIdx.y * 128;
    const int colBase = blockIdx.x * 128;

    const int lr = tid & 127;        // 0..127 (tile row for loading)
    const int lk = (tid >> 7) * 4;   // 0 or 4 (k offset for loading)
    const float* Ap = A + (size_t)(rowBase + lr) * NU;
    const float* Wp = W + (size_t)(colBase + lr) * NU;

    float acc[8][8];
#pragma unroll
    for (int i = 0; i < 8; i++)
#pragma unroll
        for (int j = 0; j < 8; j++) acc[i][j] = 0.f;

    for (int k0 = 0; k0 < NU; k0 += 8) {
        float4 a4 = *(const float4*)(Ap + k0 + lk);
        float4 b4 = *(const float4*)(Wp + k0 + lk);
        __syncthreads();
        As[lk + 0][lr] = a4.x; As[lk + 1][lr] = a4.y;
        As[lk + 2][lr] = a4.z; As[lk + 3][lr] = a4.w;
        Bs[lk + 0][lr] = b4.x; Bs[lk + 1][lr] = b4.y;
        Bs[lk + 2][lr] = b4.z; Bs[lk + 3][lr] = b4.w;
        __syncthreads();
#pragma unroll
        for (int kk = 0; kk < 8; kk++) {
            float4 a0 = *(const float4*)&As[kk][ty * 8];
            float4 a1 = *(const float4*)&As[kk][ty * 8 + 4];
            float4 b0 = *(const float4*)&Bs[kk][tx * 8];
            float4 b1 = *(const float4*)&Bs[kk][tx * 8 + 4];
            float ar[8] = {a0.x, a0.y, a0.z, a0.w, a1.x, a1.y, a1.z, a1.w};
            float br[8] = {b0.x, b0.y, b0.z, b0.w, b1.x, b1.y, b1.z, b1.w};
#pragma unroll
            for (int i = 0; i < 8; i++)
#pragma unroll
                for (int j = 0; j < 8; j++)
                    acc[i][j] += ar[i] * br[j];
        }
    }

    // Epilogue: add bias, write out.
    const int n0 = colBase + tx * 8;
    float bvals[8];
#pragma unroll
    for (int j = 0; j < 8; j++) bvals[j] = bias[n0 + j];

#pragma unroll
    for (int i = 0; i < 8; i++) {
        const int m = rowBase + ty * 8 + i;
        float4 o0, o1;
        o0.x = acc[i][0] + bvals[0]; o0.y = acc[i][1] + bvals[1];
        o0.z = acc[i][2] + bvals[2]; o0.w = acc[i][3] + bvals[3];
        o1.x = acc[i][4] + bvals[4]; o1.y = acc[i][5] + bvals[5];
        o1.z = acc[i][6] + bvals[6]; o1.w = acc[i][7] + bvals[7];
        if (mode == 0) {
            *(float4*)&C[(size_t)m * NU + n0] = o0;
            *(float4*)&C[(size_t)m * NU + n0 + 4] = o1;
        } else {
            // head-split: 8 consecutive cols never cross a 64-wide head boundary
            const int b = m >> 11;       // /2048
            const int t = m & 2047;
            const int h = n0 >> 6;       // /64
            const int d = n0 & 63;
            const size_t idx = (((size_t)(b * HH + h) * TT) + t) * DD + d;
            *(float4*)&C[idx] = o0;
            *(float4*)&C[idx + 4] = o1;
        }
    }
}

// ---------------------------------------------------------------------------
// Flash attention (non-causal), fp32, per (b,h).
// Grid: (T/64, B*H). 256 threads. BQ=BKV=64, D=64.
// smem (dynamic): Qt[d][q], Kt[d][j] (transposed), Vs[j][d], Ss[q][j],
//                 all stride 68; + m/l/alpha rows.
// Writes ctx in (b,t,h,d) layout = (8192,1024) row-major.
// ---------------------------------------------------------------------------
#define ATT_STRIDE 68
#define ATT_SMEM_FLOATS (4 * 64 * ATT_STRIDE + 3 * 64)
#define ATT_SMEM_BYTES (ATT_SMEM_FLOATS * 4)

__global__ __launch_bounds__(256) void attn_kernel(float* __restrict__ ctx)
{
    extern __shared__ float sm[];
    float* Qt = sm;                       // [64][68]  Qt[d*68 + q]
    float* Kt = Qt + 64 * ATT_STRIDE;     // [64][68]  Kt[d*68 + j]
    float* Vs = Kt + 64 * ATT_STRIDE;     // [64][68]  Vs[j*68 + d]
    float* Ss = Vs + 64 * ATT_STRIDE;     // [64][68]  Ss[q*68 + j]
    float* mrow = Ss + 64 * ATT_STRIDE;   // [64] running max
    float* lrow = mrow + 64;              // [64] running sum
    float* arow = lrow + 64;              // [64] alpha (rescale factor)

    const int tid = threadIdx.x;
    const int bh = blockIdx.y;            // b*H + h
    const int q0 = blockIdx.x * 64;

    const float* Qg = g_Q + ((size_t)bh * TT + q0) * DD;
    const float* Kg = g_K + (size_t)bh * TT * DD;
    const float* Vg = g_V + (size_t)bh * TT * DD;

    if (tid < 64) { mrow[tid] = -1e30f; lrow[tid] = 0.f; }

    // Load Q tile transposed: Qt[d][q]
    {
        const int r = tid >> 2;          // query row 0..63
        const int c4 = (tid & 3) * 16;   // d start
        const float4* src = (const float4*)(Qg + (size_t)r * DD + c4);
#pragma unroll
        for (int i = 0; i < 4; i++) {
            float4 v = src[i];
            const int d = c4 + i * 4;
            Qt[(d + 0) * ATT_STRIDE + r] = v.x;
            Qt[(d + 1) * ATT_STRIDE + r] = v.y;
            Qt[(d + 2) * ATT_STRIDE + r] = v.z;
            Qt[(d + 3) * ATT_STRIDE + r] = v.w;
        }
    }

    const int tq = tid >> 4;   // 0..15 query group (4 rows)
    const int tj = tid & 15;   // 0..15 key/d group (4 cols)

    float o[4][4];
#pragma unroll
    for (int i = 0; i < 4; i++)
#pragma unroll
        for (int j = 0; j < 4; j++) o[i][j] = 0.f;

    for (int jt = 0; jt < TT / 64; jt++) {
        __syncthreads();  // protect prior-iter Kt/Vs/Ss readers

        // Load K transposed + V row-major
        {
            const int r = tid >> 2;
            const int c4 = (tid & 3) * 16;
            const float4* ks = (const float4*)(Kg + ((size_t)(jt * 64 + r)) * DD + c4);
            const float4* vsg = (const float4*)(Vg + ((size_t)(jt * 64 + r)) * DD + c4);
#pragma unroll
            for (int i = 0; i < 4; i++) {
                float4 kv = ks[i];
                const int d = c4 + i * 4;
                Kt[(d + 0) * ATT_STRIDE + r] = kv.x;
                Kt[(d + 1) * ATT_STRIDE + r] = kv.y;
                Kt[(d + 2) * ATT_STRIDE + r] = kv.z;
                Kt[(d + 3) * ATT_STRIDE + r] = kv.w;
                float4 vv = vsg[i];
                *(float4*)&Vs[r * ATT_STRIDE + d] = vv;
            }
        }
        __syncthreads();

        // S = (Q K^T) * 1/sqrt(D)
        float s[4][4];
#pragma unroll
        for (int i = 0; i < 4; i++)
#pragma unroll
            for (int j = 0; j < 4; j++) s[i][j] = 0.f;

#pragma unroll 8
        for (int kk = 0; kk < 64; kk++) {
            float4 qv = *(const float4*)&Qt[kk * ATT_STRIDE + tq * 4];
            float4 kv = *(const float4*)&Kt[kk * ATT_STRIDE + tj * 4];
            float qr[4] = {qv.x, qv.y, qv.z, qv.w};
            float kr[4] = {kv.x, kv.y, kv.z, kv.w};
#pragma unroll
            for (int i = 0; i < 4; i++)
#pragma unroll
                for (int j = 0; j < 4; j++)
                    s[i][j] += qr[i] * kr[j];
        }
#pragma unroll
        for (int i = 0; i < 4; i++) {
            float4 sv;
            sv.x = s[i][0] * 0.125f; sv.y = s[i][1] * 0.125f;
            sv.z = s[i][2] * 0.125f; sv.w = s[i][3] * 0.125f;
            *(float4*)&Ss[(tq * 4 + i) * ATT_STRIDE + tj * 4] = sv;
        }
        __syncthreads();

        // Online softmax bookkeeping: one thread per query row
        if (tid < 64) {
            const int r = tid;
            float* row = Ss + r * ATT_STRIDE;
            float mt = -1e30f;
#pragma unroll 8
            for (int j = 0; j < 64; j++) mt = fmaxf(mt, row[j]);
            const float mold = mrow[r];
            const float mnew = fmaxf(mold, mt);
            const float al = __expf(mold - mnew);
            float sum = 0.f;
#pragma unroll 8
            for (int j = 0; j < 64; j++) {
                float p = __expf(row[j] - mnew);
                row[j] = p;
                sum += p;
            }
            lrow[r] = lrow[r] * al + sum;
            mrow[r] = mnew;
            arow[r] = al;
        }
        __syncthreads();

        // Rescale accumulators + P @ V
        float al[4];
#pragma unroll
        for (int i = 0; i < 4; i++) al[i] = arow[tq * 4 + i];
#pragma unroll
        for (int i = 0; i < 4; i++)
#pragma unroll
            for (int j = 0; j < 4; j++) o[i][j] *= al[i];

#pragma unroll 8
        for (int j = 0; j < 64; j++) {
            float4 vv = *(const float4*)&Vs[j * ATT_STRIDE + tj * 4];
#pragma unroll
            for (int i = 0; i < 4; i++) {
                const float p = Ss[(tq * 4 + i) * ATT_STRIDE + j];
                o[i][0] += p * vv.x;
                o[i][1] += p * vv.y;
                o[i][2] += p * vv.z;
                o[i][3] += p * vv.w;
            }
        }
    }

    // Normalize and write ctx in (b,t,h,d) layout
    const int b = bh >> 4;   // /H
    const int h = bh & 15;
#pragma unroll
    for (int i = 0; i < 4; i++) {
        const int q = tq * 4 + i;
        const float inv = 1.f / lrow[q];
        const size_t idx = (size_t)(b * TT + q0 + q) * NU + h * DD + tj * 4;
        float4 ov;
        ov.x = o[i][0] * inv; ov.y = o[i][1] * inv;
        ov.z = o[i][2] * inv; ov.w = o[i][3] * inv;
        *(float4*)&ctx[idx] = ov;
    }
}

// ---------------------------------------------------------------------------
// Launch
// ---------------------------------------------------------------------------
extern "C" void kernel_launch(void* const* d_in, const int* in_sizes, int n_in,
                              void* d_out, int out_size)
{
    const float* x  = (const float*)d_in[0];
    const float* Wq = (const float*)d_in[1];
    const float* bq = (const float*)d_in[2];
    const float* Wk = (const float*)d_in[3];
    const float* bk = (const float*)d_in[4];
    const float* Wv = (const float*)d_in[5];
    const float* bv = (const float*)d_in[6];
    const float* Wo = (const float*)d_in[7];
    const float* bo = (const float*)d_in[8];
    float* out = (float*)d_out;

    float *Qp, *Kp, *Vp, *Cp;
    cudaGetSymbolAddress((void**)&Qp, g_Q);
    cudaGetSymbolAddress((void**)&Kp, g_K);
    cudaGetSymbolAddress((void**)&Vp, g_V);
    cudaGetSymbolAddress((void**)&Cp, g_ctx);

    const dim3 gGemm(NU / 128, MM / 128);  // (8, 64)

    gemm_nt<<<gGemm, 256>>>(x, Wq, bq, Qp, 1);
    gemm_nt<<<gGemm, 256>>>(x, Wk, bk, Kp, 1);
    gemm_nt<<<gGemm, 256>>>(x, Wv, bv, Vp, 1);

    cudaFuncSetAttribute(attn_kernel,
                         cudaFuncAttributeMaxDynamicSharedMemorySize,
                         ATT_SMEM_BYTES);
    attn_kernel<<<dim3(TT / 64, BB * HH), 256, ATT_SMEM_BYTES>>>(Cp);

    gemm_nt<<<gGemm, 256>>>(Cp, Wo, bo, out, 0);
}

// round 4
// speedup vs baseline: 1.3462x; 1.3462x over previous
#include <cuda_runtime.h>
#include <cuda_bf16.h>
#include <math.h>

// Problem constants
#define BB 4
#define TT 2048
#define HH 16
#define DD 64
#define NU 1024
#define MM (BB * TT)  // 8192

// Scratch (device globals: allocation-free)
__device__ float g_Q[(size_t)MM * NU];
__device__ float g_K[(size_t)MM * NU];
__device__ float g_V[(size_t)MM * NU];
__device__ __nv_bfloat16 g_xhi[(size_t)MM * NU];
__device__ __nv_bfloat16 g_xlo[(size_t)MM * NU];
__device__ __nv_bfloat16 g_whi[4 * (size_t)NU * NU];
__device__ __nv_bfloat16 g_wlo[4 * (size_t)NU * NU];
__device__ __nv_bfloat16 g_chi[(size_t)MM * NU];
__device__ __nv_bfloat16 g_clo[(size_t)MM * NU];

// ---------------------------------------------------------------------------
// Split fp32 -> bf16 hi + bf16 lo  (x = hi + lo, lo = bf16(x - hi))
// ---------------------------------------------------------------------------
__global__ __launch_bounds__(256) void split_convert(
    const float4* __restrict__ in, uint2* __restrict__ hi,
    uint2* __restrict__ lo, int n4)
{
    int i = blockIdx.x * blockDim.x + threadIdx.x;
    if (i >= n4) return;
    float4 v = in[i];
    __nv_bfloat16 h0 = __float2bfloat16_rn(v.x);
    __nv_bfloat16 h1 = __float2bfloat16_rn(v.y);
    __nv_bfloat16 h2 = __float2bfloat16_rn(v.z);
    __nv_bfloat16 h3 = __float2bfloat16_rn(v.w);
    __nv_bfloat16 l0 = __float2bfloat16_rn(v.x - __bfloat162float(h0));
    __nv_bfloat16 l1 = __float2bfloat16_rn(v.y - __bfloat162float(h1));
    __nv_bfloat16 l2 = __float2bfloat16_rn(v.z - __bfloat162float(h2));
    __nv_bfloat16 l3 = __float2bfloat16_rn(v.w - __bfloat162float(h3));
    union { __nv_bfloat16 b[4]; uint2 u; } ph, pl;
    ph.b[0] = h0; ph.b[1] = h1; ph.b[2] = h2; ph.b[3] = h3;
    pl.b[0] = l0; pl.b[1] = l1; pl.b[2] = l2; pl.b[3] = l3;
    hi[i] = ph.u;
    lo[i] = pl.u;
}

// ---------------------------------------------------------------------------
// Split-bf16 tensor-core GEMM (NT): C[m,n] = sum_k A[m,k]*W[n,k] + bias[n]
//   A ~ Ahi+Alo, W ~ Bhi+Blo;  C = Ahi*Bhi + Ahi*Blo + Alo*Bhi  (fp32 accum)
// Tile: 128x128, KC=32. 256 threads = 8 warps (2 m x 4 n), warp tile 64x32.
// mma.sync.m16n8k16.bf16, ldmatrix from smem (stride 40 bf16: conflict-free).
// mode 0: C[m*1024+n];  mode 1: head-split C[((b*16+h)*2048+t)*64+d]
// ---------------------------------------------------------------------------
#define GBM 128
#define GBN 128
#define GKC 32
#define GLD 40  // smem row stride in bf16 (80B): conflict-free for 8-row ldmatrix

__device__ __forceinline__ void mma_bf16(float* d, const unsigned* a, const unsigned* b)
{
    asm volatile(
        "mma.sync.aligned.m16n8k16.row.col.f32.bf16.bf16.f32 "
        "{%0,%1,%2,%3}, {%4,%5,%6,%7}, {%8,%9}, {%0,%1,%2,%3};\n"
        : "+f"(d[0]), "+f"(d[1]), "+f"(d[2]), "+f"(d[3])
        : "r"(a[0]), "r"(a[1]), "r"(a[2]), "r"(a[3]), "r"(b[0]), "r"(b[1]));
}

__device__ __forceinline__ void ldsm_x4(unsigned* r, unsigned addr)
{
    asm volatile("ldmatrix.sync.aligned.m8n8.x4.shared.b16 {%0,%1,%2,%3}, [%4];\n"
                 : "=r"(r[0]), "=r"(r[1]), "=r"(r[2]), "=r"(r[3]) : "r"(addr));
}

__device__ __forceinline__ void ldsm_x2(unsigned* r, unsigned addr)
{
    asm volatile("ldmatrix.sync.aligned.m8n8.x2.shared.b16 {%0,%1}, [%2];\n"
                 : "=r"(r[0]), "=r"(r[1]) : "r"(addr));
}

__global__ __launch_bounds__(256) void gemm_bf16_split(
    const __nv_bfloat16* __restrict__ Ahi, const __nv_bfloat16* __restrict__ Alo,
    const __nv_bfloat16* __restrict__ Bhi, const __nv_bfloat16* __restrict__ Blo,
    const float* __restrict__ bias, float* __restrict__ C, int mode)
{
    __shared__ __nv_bfloat16 sAh[GBM][GLD];
    __shared__ __nv_bfloat16 sAl[GBM][GLD];
    __shared__ __nv_bfloat16 sBh[GBN][GLD];
    __shared__ __nv_bfloat16 sBl[GBN][GLD];

    const int tid = threadIdx.x;
    const int wid = tid >> 5;
    const int lane = tid & 31;
    const int wm = wid >> 2;   // 0..1 : 64 rows each
    const int wn = wid & 3;    // 0..3 : 32 cols each
    const int rowBase = blockIdx.y * GBM;
    const int colBase = blockIdx.x * GBN;

    // Loader indices: each thread loads 16 bf16 (2x float4) per matrix
    const int lrow = tid >> 1;           // 0..127
    const int lk = (tid & 1) * 16;       // 0 or 16

    const __nv_bfloat16* ApH = Ahi + (size_t)(rowBase + lrow) * NU + lk;
    const __nv_bfloat16* ApL = Alo + (size_t)(rowBase + lrow) * NU + lk;
    const __nv_bfloat16* BpH = Bhi + (size_t)(colBase + lrow) * NU + lk;
    const __nv_bfloat16* BpL = Blo + (size_t)(colBase + lrow) * NU + lk;

    // ldmatrix base addresses (byte offsets within k-chunk added per step)
    unsigned aAddrH[4], aAddrL[4], bAddrH[4], bAddrL[4];
#pragma unroll
    for (int mt = 0; mt < 4; mt++) {
        const int r = wm * 64 + mt * 16 + (lane & 15);
        const int c = ((lane >> 4) & 1) * 8;
        aAddrH[mt] = (unsigned)__cvta_generic_to_shared(&sAh[r][c]);
        aAddrL[mt] = (unsigned)__cvta_generic_to_shared(&sAl[r][c]);
    }
#pragma unroll
    for (int nt = 0; nt < 4; nt++) {
        const int r = wn * 32 + nt * 8 + (lane & 7);
        const int c = ((lane >> 3) & 1) * 8;
        bAddrH[nt] = (unsigned)__cvta_generic_to_shared(&sBh[r][c]);
        bAddrL[nt] = (unsigned)__cvta_generic_to_shared(&sBl[r][c]);
    }

    float acc[4][4][4];
#pragma unroll
    for (int i = 0; i < 4; i++)
#pragma unroll
        for (int j = 0; j < 4; j++)
#pragma unroll
            for (int c = 0; c < 4; c++) acc[i][j][c] = 0.f;

    for (int k0 = 0; k0 < NU; k0 += GKC) {
        // Prefetch global -> regs
        float4 ah0 = *(const float4*)(ApH + k0);
        float4 ah1 = *(const float4*)(ApH + k0 + 8);
        float4 al0 = *(const float4*)(ApL + k0);
        float4 al1 = *(const float4*)(ApL + k0 + 8);
        float4 bh0 = *(const float4*)(BpH + k0);
        float4 bh1 = *(const float4*)(BpH + k0 + 8);
        float4 bl0 = *(const float4*)(BpL + k0);
        float4 bl1 = *(const float4*)(BpL + k0 + 8);
        __syncthreads();
        *(float4*)&sAh[lrow][lk] = ah0; *(float4*)&sAh[lrow][lk + 8] = ah1;
        *(float4*)&sAl[lrow][lk] = al0; *(float4*)&sAl[lrow][lk + 8] = al1;
        *(float4*)&sBh[lrow][lk] = bh0; *(float4*)&sBh[lrow][lk + 8] = bh1;
        *(float4*)&sBl[lrow][lk] = bl0; *(float4*)&sBl[lrow][lk + 8] = bl1;
        __syncthreads();

#pragma unroll
        for (int ks = 0; ks < 2; ks++) {
            const unsigned koff = ks * 16 * 2;  // 16 bf16 = 32 bytes
            unsigned bh[4][2], bl[4][2];
#pragma unroll
            for (int nt = 0; nt < 4; nt++) {
                ldsm_x2(bh[nt], bAddrH[nt] + koff);
                ldsm_x2(bl[nt], bAddrL[nt] + koff);
            }
#pragma unroll
            for (int mt = 0; mt < 4; mt++) {
                unsigned ah[4], al[4];
                ldsm_x4(ah, aAddrH[mt] + koff);
                ldsm_x4(al, aAddrL[mt] + koff);
                // term 1: hi*hi  (reuse-distance 4 on each accumulator)
#pragma unroll
                for (int nt = 0; nt < 4; nt++) mma_bf16(acc[mt][nt], ah, bh[nt]);
                // term 2: hi*lo
#pragma unroll
                for (int nt = 0; nt < 4; nt++) mma_bf16(acc[mt][nt], ah, bl[nt]);
                // term 3: lo*hi
#pragma unroll
                for (int nt = 0; nt < 4; nt++) mma_bf16(acc[mt][nt], al, bh[nt]);
            }
        }
    }

    // Epilogue
#pragma unroll
    for (int mt = 0; mt < 4; mt++) {
#pragma unroll
        for (int nt = 0; nt < 4; nt++) {
            const int m = rowBase + wm * 64 + mt * 16 + (lane >> 2);
            const int n = colBase + wn * 32 + nt * 8 + (lane & 3) * 2;
            const float b0 = bias[n];
            const float b1 = bias[n + 1];
            float2 v0 = make_float2(acc[mt][nt][0] + b0, acc[mt][nt][1] + b1);
            float2 v1 = make_float2(acc[mt][nt][2] + b0, acc[mt][nt][3] + b1);
            if (mode == 0) {
                *(float2*)&C[(size_t)m * NU + n] = v0;
                *(float2*)&C[(size_t)(m + 8) * NU + n] = v1;
            } else {
                const int h = n >> 6, d = n & 63;
                {
                    const int b = m >> 11, t = m & 2047;
                    const size_t idx = (((size_t)(b * HH + h) * TT) + t) * DD + d;
                    *(float2*)&C[idx] = v0;
                }
                {
                    const int m2 = m + 8;
                    const int b = m2 >> 11, t = m2 & 2047;
                    const size_t idx = (((size_t)(b * HH + h) * TT) + t) * DD + d;
                    *(float2*)&C[idx] = v1;
                }
            }
        }
    }
}

// ---------------------------------------------------------------------------
// Flash attention (non-causal), fp32, per (b,h).
// Grid: (T/64, B*H). 256 threads. BQ=BKV=64, D=64.
// Ss holds S/P TRANSPOSED: Ss[j][q] so the PV loop reads float4 in q.
// Epilogue writes ctx directly as split bf16 (hi/lo) in (b,t,h,d) layout.
// ---------------------------------------------------------------------------
#define ATT_STRIDE 68
#define ATT_SMEM_FLOATS (4 * 64 * ATT_STRIDE + 3 * 64)
#define ATT_SMEM_BYTES (ATT_SMEM_FLOATS * 4)

__global__ __launch_bounds__(256) void attn_kernel()
{
    extern __shared__ float sm[];
    float* Qt = sm;                       // [64][68]  Qt[d*68 + q]
    float* Kt = Qt + 64 * ATT_STRIDE;     // [64][68]  Kt[d*68 + j]
    float* Vs = Kt + 64 * ATT_STRIDE;     // [64][68]  Vs[j*68 + d]
    float* Ss = Vs + 64 * ATT_STRIDE;     // [64][68]  Ss[j*68 + q]  (transposed!)
    float* mrow = Ss + 64 * ATT_STRIDE;   // [64]
    float* lrow = mrow + 64;              // [64]
    float* arow = lrow + 64;              // [64]

    const int tid = threadIdx.x;
    const int bh = blockIdx.y;
    const int q0 = blockIdx.x * 64;

    const float* Qg = g_Q + ((size_t)bh * TT + q0) * DD;
    const float* Kg = g_K + (size_t)bh * TT * DD;
    const float* Vg = g_V + (size_t)bh * TT * DD;

    if (tid < 64) { mrow[tid] = -1e30f; lrow[tid] = 0.f; }

    {
        const int r = tid >> 2;
        const int c4 = (tid & 3) * 16;
        const float4* src = (const float4*)(Qg + (size_t)r * DD + c4);
#pragma unroll
        for (int i = 0; i < 4; i++) {
            float4 v = src[i];
            const int d = c4 + i * 4;
            Qt[(d + 0) * ATT_STRIDE + r] = v.x;
            Qt[(d + 1) * ATT_STRIDE + r] = v.y;
            Qt[(d + 2) * ATT_STRIDE + r] = v.z;
            Qt[(d + 3) * ATT_STRIDE + r] = v.w;
        }
    }

    const int tq = tid >> 4;
    const int tj = tid & 15;

    float o[4][4];
#pragma unroll
    for (int i = 0; i < 4; i++)
#pragma unroll
        for (int j = 0; j < 4; j++) o[i][j] = 0.f;

    for (int jt = 0; jt < TT / 64; jt++) {
        __syncthreads();

        {
            const int r = tid >> 2;
            const int c4 = (tid & 3) * 16;
            const float4* ks = (const float4*)(Kg + ((size_t)(jt * 64 + r)) * DD + c4);
            const float4* vsg = (const float4*)(Vg + ((size_t)(jt * 64 + r)) * DD + c4);
#pragma unroll
            for (int i = 0; i < 4; i++) {
                float4 kv = ks[i];
                const int d = c4 + i * 4;
                Kt[(d + 0) * ATT_STRIDE + r] = kv.x;
                Kt[(d + 1) * ATT_STRIDE + r] = kv.y;
                Kt[(d + 2) * ATT_STRIDE + r] = kv.z;
                Kt[(d + 3) * ATT_STRIDE + r] = kv.w;
                float4 vv = vsg[i];
                *(float4*)&Vs[r * ATT_STRIDE + d] = vv;
            }
        }
        __syncthreads();

        float s[4][4];
#pragma unroll
        for (int i = 0; i < 4; i++)
#pragma unroll
            for (int j = 0; j < 4; j++) s[i][j] = 0.f;

#pragma unroll 8
        for (int kk = 0; kk < 64; kk++) {
            float4 qv = *(const float4*)&Qt[kk * ATT_STRIDE + tq * 4];
            float4 kv = *(const float4*)&Kt[kk * ATT_STRIDE + tj * 4];
            float qr[4] = {qv.x, qv.y, qv.z, qv.w};
            float kr[4] = {kv.x, kv.y, kv.z, kv.w};
#pragma unroll
            for (int i = 0; i < 4; i++)
#pragma unroll
                for (int j = 0; j < 4; j++)
                    s[i][j] += qr[i] * kr[j];
        }
        // Store TRANSPOSED: Ss[j][q], contiguous float4 in q
#pragma unroll
        for (int j = 0; j < 4; j++) {
            float4 sv;
            sv.x = s[0][j] * 0.125f; sv.y = s[1][j] * 0.125f;
            sv.z = s[2][j] * 0.125f; sv.w = s[3][j] * 0.125f;
            *(float4*)&Ss[(tj * 4 + j) * ATT_STRIDE + tq * 4] = sv;
        }
        __syncthreads();

        if (tid < 64) {
            const int r = tid;
            float mt = -1e30f;
#pragma unroll 8
            for (int j = 0; j < 64; j++) mt = fmaxf(mt, Ss[j * ATT_STRIDE + r]);
            const float mold = mrow[r];
            const float mnew = fmaxf(mold, mt);
            const float al = __expf(mold - mnew);
            float sum = 0.f;
#pragma unroll 8
            for (int j = 0; j < 64; j++) {
                float p = __expf(Ss[j * ATT_STRIDE + r] - mnew);
                Ss[j * ATT_STRIDE + r] = p;
                sum += p;
            }
            lrow[r] = lrow[r] * al + sum;
            mrow[r] = mnew;
            arow[r] = al;
        }
        __syncthreads();

        float al[4];
#pragma unroll
        for (int i = 0; i < 4; i++) al[i] = arow[tq * 4 + i];
#pragma unroll
        for (int i = 0; i < 4; i++)
#pragma unroll
            for (int j = 0; j < 4; j++) o[i][j] *= al[i];

#pragma unroll 8
        for (int j = 0; j < 64; j++) {
            float4 vv = *(const float4*)&Vs[j * ATT_STRIDE + tj * 4];
            float4 pv = *(const float4*)&Ss[j * ATT_STRIDE + tq * 4];
            o[0][0] += pv.x * vv.x; o[0][1] += pv.x * vv.y;
            o[0][2] += pv.x * vv.z; o[0][3] += pv.x * vv.w;
            o[1][0] += pv.y * vv.x; o[1][1] += pv.y * vv.y;
            o[1][2] += pv.y * vv.z; o[1][3] += pv.y * vv.w;
            o[2][0] += pv.z * vv.x; o[2][1] += pv.z * vv.y;
            o[2][2] += pv.z * vv.z; o[2][3] += pv.z * vv.w;
            o[3][0] += pv.w * vv.x; o[3][1] += pv.w * vv.y;
            o[3][2] += pv.w * vv.z; o[3][3] += pv.w * vv.w;
        }
    }

    // Epilogue: normalize, split into bf16 hi/lo, write (b,t,h,d)
    const int b = bh >> 4;
    const int h = bh & 15;
#pragma unroll
    for (int i = 0; i < 4; i++) {
        const int q = tq * 4 + i;
        const float inv = 1.f / lrow[q];
        const size_t idx = (size_t)(b * TT + q0 + q) * NU + h * DD + tj * 4;
        float v[4];
#pragma unroll
        for (int j = 0; j < 4; j++) v[j] = o[i][j] * inv;
        __nv_bfloat16 hb[4], lb[4];
#pragma unroll
        for (int j = 0; j < 4; j++) {
            hb[j] = __float2bfloat16_rn(v[j]);
            lb[j] = __float2bfloat16_rn(v[j] - __bfloat162float(hb[j]));
        }
        __nv_bfloat162 h01; h01.x = hb[0]; h01.y = hb[1];
        __nv_bfloat162 h23; h23.x = hb[2]; h23.y = hb[3];
        __nv_bfloat162 l01; l01.x = lb[0]; l01.y = lb[1];
        __nv_bfloat162 l23; l23.x = lb[2]; l23.y = lb[3];
        *(__nv_bfloat162*)&g_chi[idx] = h01;
        *(__nv_bfloat162*)&g_chi[idx + 2] = h23;
        *(__nv_bfloat162*)&g_clo[idx] = l01;
        *(__nv_bfloat162*)&g_clo[idx + 2] = l23;
    }
}

// ---------------------------------------------------------------------------
// Launch
// ---------------------------------------------------------------------------
extern "C" void kernel_launch(void* const* d_in, const int* in_sizes, int n_in,
                              void* d_out, int out_size)
{
    const float* x  = (const float*)d_in[0];
    const float* Wq = (const float*)d_in[1];
    const float* bq = (const float*)d_in[2];
    const float* Wk = (const float*)d_in[3];
    const float* bk = (const float*)d_in[4];
    const float* Wv = (const float*)d_in[5];
    const float* bv = (const float*)d_in[6];
    const float* Wo = (const float*)d_in[7];
    const float* bo = (const float*)d_in[8];
    float* out = (float*)d_out;

    float *Qp, *Kp, *Vp;
    __nv_bfloat16 *xhi, *xlo, *whi, *wlo, *chi, *clo;
    cudaGetSymbolAddress((void**)&Qp, g_Q);
    cudaGetSymbolAddress((void**)&Kp, g_K);
    cudaGetSymbolAddress((void**)&Vp, g_V);
    cudaGetSymbolAddress((void**)&xhi, g_xhi);
    cudaGetSymbolAddress((void**)&xlo, g_xlo);
    cudaGetSymbolAddress((void**)&whi, g_whi);
    cudaGetSymbolAddress((void**)&wlo, g_wlo);
    cudaGetSymbolAddress((void**)&chi, g_chi);
    cudaGetSymbolAddress((void**)&clo, g_clo);

    // Split conversions
    const int n4x = (int)((size_t)MM * NU / 4);
    split_convert<<<(n4x + 255) / 256, 256>>>((const float4*)x, (uint2*)xhi,
                                              (uint2*)xlo, n4x);
    const int n4w = NU * NU / 4;
    const float* Ws[4] = {Wq, Wk, Wv, Wo};
    for (int w = 0; w < 4; w++) {
        split_convert<<<(n4w + 255) / 256, 256>>>(
            (const float4*)Ws[w],
            (uint2*)(whi + (size_t)w * NU * NU),
            (uint2*)(wlo + (size_t)w * NU * NU), n4w);
    }

    const dim3 gGemm(NU / GBN, MM / GBM);  // (8, 64)

    gemm_bf16_split<<<gGemm, 256>>>(xhi, xlo, whi + 0 * (size_t)NU * NU,
                                    wlo + 0 * (size_t)NU * NU, bq, Qp, 1);
    gemm_bf16_split<<<gGemm, 256>>>(xhi, xlo, whi + 1 * (size_t)NU * NU,
                                    wlo + 1 * (size_t)NU * NU, bk, Kp, 1);
    gemm_bf16_split<<<gGemm, 256>>>(xhi, xlo, whi + 2 * (size_t)NU * NU,
                                    wlo + 2 * (size_t)NU * NU, bv, Vp, 1);

    cudaFuncSetAttribute(attn_kernel,
                         cudaFuncAttributeMaxDynamicSharedMemorySize,
                         ATT_SMEM_BYTES);
    attn_kernel<<<dim3(TT / 64, BB * HH), 256, ATT_SMEM_BYTES>>>();

    gemm_bf16_split<<<gGemm, 256>>>(chi, clo, whi + 3 * (size_t)NU * NU,
                                    wlo + 3 * (size_t)NU * NU, bo, out, 0);
}

// round 7
// speedup vs baseline: 2.5896x; 1.9237x over previous
#include <cuda_runtime.h>
#include <cuda_bf16.h>
#include <math.h>

// Problem constants
#define BB 4
#define TT 2048
#define HH 16
#define DD 64
#define NU 1024
#define MM (BB * TT)  // 8192

// Scratch (device globals: allocation-free)
__device__ __nv_bfloat16 g_xhi[(size_t)MM * NU];
__device__ __nv_bfloat16 g_xlo[(size_t)MM * NU];
__device__ __nv_bfloat16 g_whi[4 * (size_t)NU * NU];
__device__ __nv_bfloat16 g_wlo[4 * (size_t)NU * NU];
__device__ __nv_bfloat16 g_qh[(size_t)MM * NU];
__device__ __nv_bfloat16 g_ql[(size_t)MM * NU];
__device__ __nv_bfloat16 g_kh[(size_t)MM * NU];
__device__ __nv_bfloat16 g_kl[(size_t)MM * NU];
__device__ __nv_bfloat16 g_vh[(size_t)MM * NU];
__device__ __nv_bfloat16 g_vl[(size_t)MM * NU];
__device__ __nv_bfloat16 g_chi[(size_t)MM * NU];
__device__ __nv_bfloat16 g_clo[(size_t)MM * NU];

// ---------------------------------------------------------------------------
// Split fp32 -> bf16 hi + bf16 lo
// ---------------------------------------------------------------------------
__global__ __launch_bounds__(256) void split_convert(
    const float4* __restrict__ in, uint2* __restrict__ hi,
    uint2* __restrict__ lo, int n4)
{
    int i = blockIdx.x * blockDim.x + threadIdx.x;
    if (i >= n4) return;
    float4 v = in[i];
    __nv_bfloat16 h0 = __float2bfloat16_rn(v.x);
    __nv_bfloat16 h1 = __float2bfloat16_rn(v.y);
    __nv_bfloat16 h2 = __float2bfloat16_rn(v.z);
    __nv_bfloat16 h3 = __float2bfloat16_rn(v.w);
    __nv_bfloat16 l0 = __float2bfloat16_rn(v.x - __bfloat162float(h0));
    __nv_bfloat16 l1 = __float2bfloat16_rn(v.y - __bfloat162float(h1));
    __nv_bfloat16 l2 = __float2bfloat16_rn(v.z - __bfloat162float(h2));
    __nv_bfloat16 l3 = __float2bfloat16_rn(v.w - __bfloat162float(h3));
    union { __nv_bfloat16 b[4]; uint2 u; } ph, pl;
    ph.b[0] = h0; ph.b[1] = h1; ph.b[2] = h2; ph.b[3] = h3;
    pl.b[0] = l0; pl.b[1] = l1; pl.b[2] = l2; pl.b[3] = l3;
    hi[i] = ph.u;
    lo[i] = pl.u;
}

// ---------------------------------------------------------------------------
// MMA / ldmatrix helpers
// ---------------------------------------------------------------------------
__device__ __forceinline__ void mma_bf16(float* d, const unsigned* a, const unsigned* b)
{
    asm volatile(
        "mma.sync.aligned.m16n8k16.row.col.f32.bf16.bf16.f32 "
        "{%0,%1,%2,%3}, {%4,%5,%6,%7}, {%8,%9}, {%0,%1,%2,%3};\n"
        : "+f"(d[0]), "+f"(d[1]), "+f"(d[2]), "+f"(d[3])
        : "r"(a[0]), "r"(a[1]), "r"(a[2]), "r"(a[3]), "r"(b[0]), "r"(b[1]));
}

__device__ __forceinline__ void ldsm_x4(unsigned* r, unsigned addr)
{
    asm volatile("ldmatrix.sync.aligned.m8n8.x4.shared.b16 {%0,%1,%2,%3}, [%4];\n"
                 : "=r"(r[0]), "=r"(r[1]), "=r"(r[2]), "=r"(r[3]) : "r"(addr));
}

__device__ __forceinline__ void ldsm_x4t(unsigned* r, unsigned addr)
{
    asm volatile("ldmatrix.sync.aligned.m8n8.x4.trans.shared.b16 {%0,%1,%2,%3}, [%4];\n"
                 : "=r"(r[0]), "=r"(r[1]), "=r"(r[2]), "=r"(r[3]) : "r"(addr));
}

__device__ __forceinline__ unsigned pack_hi(float a, float b, float& ra, float& rb)
{
    __nv_bfloat162 h = __float22bfloat162_rn(make_float2(a, b));
    float2 hf = __bfloat1622float2(h);
    ra = a - hf.x;
    rb = b - hf.y;
    return *(unsigned*)&h;
}

__device__ __forceinline__ unsigned pack_lo(float a, float b)
{
    __nv_bfloat162 h = __float22bfloat162_rn(make_float2(a, b));
    return *(unsigned*)&h;
}

// ---------------------------------------------------------------------------
// Split-bf16 tensor-core GEMM (NT): C = A @ W^T + bias
// mode 0: fp32 out C[m*1024+n]
// mode 1: split bf16 out (Chi/Clo) in head-split layout ((b*16+h)*2048+t)*64+d
// ---------------------------------------------------------------------------
#define GBM 128
#define GBN 128
#define GKC 32
#define GLD 40

__global__ __launch_bounds__(256) void gemm_bf16_split(
    const __nv_bfloat16* __restrict__ Ahi, const __nv_bfloat16* __restrict__ Alo,
    const __nv_bfloat16* __restrict__ Bhi, const __nv_bfloat16* __restrict__ Blo,
    const float* __restrict__ bias, float* __restrict__ C,
    __nv_bfloat16* __restrict__ Chi, __nv_bfloat16* __restrict__ Clo, int mode)
{
    __shared__ __nv_bfloat16 sAh[GBM][GLD];
    __shared__ __nv_bfloat16 sAl[GBM][GLD];
    __shared__ __nv_bfloat16 sBh[GBN][GLD];
    __shared__ __nv_bfloat16 sBl[GBN][GLD];

    const int tid = threadIdx.x;
    const int wid = tid >> 5;
    const int lane = tid & 31;
    const int wm = wid >> 2;
    const int wn = wid & 3;
    const int rowBase = blockIdx.y * GBM;
    const int colBase = blockIdx.x * GBN;

    const int lrow = tid >> 1;
    const int lk = (tid & 1) * 16;

    const __nv_bfloat16* ApH = Ahi + (size_t)(rowBase + lrow) * NU + lk;
    const __nv_bfloat16* ApL = Alo + (size_t)(rowBase + lrow) * NU + lk;
    const __nv_bfloat16* BpH = Bhi + (size_t)(colBase + lrow) * NU + lk;
    const __nv_bfloat16* BpL = Blo + (size_t)(colBase + lrow) * NU + lk;

    unsigned aAddrH[4], aAddrL[4], bAddrH[4], bAddrL[4];
#pragma unroll
    for (int mt = 0; mt < 4; mt++) {
        const int r = wm * 64 + mt * 16 + (lane & 15);
        const int c = ((lane >> 4) & 1) * 8;
        aAddrH[mt] = (unsigned)__cvta_generic_to_shared(&sAh[r][c]);
        aAddrL[mt] = (unsigned)__cvta_generic_to_shared(&sAl[r][c]);
    }
#pragma unroll
    for (int nt = 0; nt < 4; nt++) {
        const int r = wn * 32 + nt * 8 + (lane & 7);
        const int c = ((lane >> 3) & 1) * 8;
        bAddrH[nt] = (unsigned)__cvta_generic_to_shared(&sBh[r][c]);
        bAddrL[nt] = (unsigned)__cvta_generic_to_shared(&sBl[r][c]);
    }

    float acc[4][4][4];
#pragma unroll
    for (int i = 0; i < 4; i++)
#pragma unroll
        for (int j = 0; j < 4; j++)
#pragma unroll
            for (int c = 0; c < 4; c++) acc[i][j][c] = 0.f;

    for (int k0 = 0; k0 < NU; k0 += GKC) {
        float4 ah0 = *(const float4*)(ApH + k0);
        float4 ah1 = *(const float4*)(ApH + k0 + 8);
        float4 al0 = *(const float4*)(ApL + k0);
        float4 al1 = *(const float4*)(ApL + k0 + 8);
        float4 bh0 = *(const float4*)(BpH + k0);
        float4 bh1 = *(const float4*)(BpH + k0 + 8);
        float4 bl0 = *(const float4*)(BpL + k0);
        float4 bl1 = *(const float4*)(BpL + k0 + 8);
        __syncthreads();
        *(float4*)&sAh[lrow][lk] = ah0; *(float4*)&sAh[lrow][lk + 8] = ah1;
        *(float4*)&sAl[lrow][lk] = al0; *(float4*)&sAl[lrow][lk + 8] = al1;
        *(float4*)&sBh[lrow][lk] = bh0; *(float4*)&sBh[lrow][lk + 8] = bh1;
        *(float4*)&sBl[lrow][lk] = bl0; *(float4*)&sBl[lrow][lk + 8] = bl1;
        __syncthreads();

#pragma unroll
        for (int ks = 0; ks < 2; ks++) {
            const unsigned koff = ks * 32;
            unsigned bh[4][4], bl[4][4];
#pragma unroll
            for (int nt = 0; nt < 4; nt++) {
                asm volatile("ldmatrix.sync.aligned.m8n8.x2.shared.b16 {%0,%1}, [%2];\n"
                             : "=r"(bh[nt][0]), "=r"(bh[nt][1]) : "r"(bAddrH[nt] + koff));
                asm volatile("ldmatrix.sync.aligned.m8n8.x2.shared.b16 {%0,%1}, [%2];\n"
                             : "=r"(bl[nt][0]), "=r"(bl[nt][1]) : "r"(bAddrL[nt] + koff));
            }
#pragma unroll
            for (int mt = 0; mt < 4; mt++) {
                unsigned ah[4], al[4];
                ldsm_x4(ah, aAddrH[mt] + koff);
                ldsm_x4(al, aAddrL[mt] + koff);
#pragma unroll
                for (int nt = 0; nt < 4; nt++) mma_bf16(acc[mt][nt], ah, bh[nt]);
#pragma unroll
                for (int nt = 0; nt < 4; nt++) mma_bf16(acc[mt][nt], ah, bl[nt]);
#pragma unroll
                for (int nt = 0; nt < 4; nt++) mma_bf16(acc[mt][nt], al, bh[nt]);
            }
        }
    }

#pragma unroll
    for (int mt = 0; mt < 4; mt++) {
#pragma unroll
        for (int nt = 0; nt < 4; nt++) {
            const int m = rowBase + wm * 64 + mt * 16 + (lane >> 2);
            const int n = colBase + wn * 32 + nt * 8 + (lane & 3) * 2;
            const float b0 = bias[n];
            const float b1 = bias[n + 1];
            float v0x = acc[mt][nt][0] + b0, v0y = acc[mt][nt][1] + b1;
            float v1x = acc[mt][nt][2] + b0, v1y = acc[mt][nt][3] + b1;
            if (mode == 0) {
                *(float2*)&C[(size_t)m * NU + n] = make_float2(v0x, v0y);
                *(float2*)&C[(size_t)(m + 8) * NU + n] = make_float2(v1x, v1y);
            } else {
                const int h = n >> 6, d = n & 63;
#pragma unroll
                for (int rr = 0; rr < 2; rr++) {
                    const int mr = m + rr * 8;
                    const int b = mr >> 11, t = mr & 2047;
                    const size_t idx = (((size_t)(b * HH + h) * TT) + t) * DD + d;
                    float vx = rr ? v1x : v0x, vy = rr ? v1y : v0y;
                    __nv_bfloat162 hh = __float22bfloat162_rn(make_float2(vx, vy));
                    float2 hf = __bfloat1622float2(hh);
                    __nv_bfloat162 ll = __float22bfloat162_rn(
                        make_float2(vx - hf.x, vy - hf.y));
                    *(__nv_bfloat162*)&Chi[idx] = hh;
                    *(__nv_bfloat162*)&Clo[idx] = ll;
                }
            }
        }
    }
}

// ---------------------------------------------------------------------------
// Tensor-core flash attention (non-causal), split-bf16, per (b,h).
// Grid: (T/128, B*H). 256 threads = 8 warps; warp owns 16 query rows.
// KV tiles of 64. All matmuls 3-term split bf16, fp32 accum.
// ---------------------------------------------------------------------------
#define ATQ 128
#define AKV 64
#define SVLD 72   // smem row stride in bf16 (144B) - conflict-free ldmatrix

__global__ __launch_bounds__(256) void attn_tc()
{
    __shared__ __nv_bfloat16 smk[4][AKV][SVLD];  // Kh, Kl, Vh, Vl (36.9KB)

    const int tid = threadIdx.x;
    const int lane = tid & 31;
    const int wid = tid >> 5;
    const int bh = blockIdx.y;
    const int q0 = blockIdx.x * ATQ;

    const size_t kvbase = (size_t)bh * TT * DD;
    const __nv_bfloat16* Qhp = g_qh + kvbase + (size_t)q0 * DD;
    const __nv_bfloat16* Qlp = g_ql + kvbase + (size_t)q0 * DD;
    const __nv_bfloat16* Khp = g_kh + kvbase;
    const __nv_bfloat16* Klp = g_kl + kvbase;
    const __nv_bfloat16* Vhp = g_vh + kvbase;
    const __nv_bfloat16* Vlp = g_vl + kvbase;

    // ---- Stage Q tile (128x64 hi/lo) into smem, load A-frags to registers ----
    __nv_bfloat16* sQh = &smk[0][0][0];
    __nv_bfloat16* sQl = &smk[2][0][0];
    {
        const int r = tid >> 1;
        const int c = (tid & 1) * 32;
        const uint4* gh = (const uint4*)(Qhp + (size_t)r * DD + c);
        const uint4* gl = (const uint4*)(Qlp + (size_t)r * DD + c);
        uint4* dh = (uint4*)(sQh + r * SVLD + c);
        uint4* dl = (uint4*)(sQl + r * SVLD + c);
#pragma unroll
        for (int i = 0; i < 4; i++) { dh[i] = gh[i]; dl[i] = gl[i]; }
    }
    __syncthreads();

    unsigned qfh[4][4], qfl[4][4];
    {
        const int qrow = wid * 16 + (lane & 15);
        const int ccol = ((lane >> 4) & 1) * 8;
#pragma unroll
        for (int kk = 0; kk < 4; kk++) {
            ldsm_x4(qfh[kk], (unsigned)__cvta_generic_to_shared(
                                 sQh + qrow * SVLD + kk * 16 + ccol));
            ldsm_x4(qfl[kk], (unsigned)__cvta_generic_to_shared(
                                 sQl + qrow * SVLD + kk * 16 + ccol));
        }
    }

    // Precomputed ldmatrix addresses
    unsigned kAddrH[4], kAddrL[4];
#pragma unroll
    for (int np = 0; np < 4; np++) {
        const int r = np * 16 + (lane & 15);
        const int c = ((lane >> 4) & 1) * 8;
        kAddrH[np] = (unsigned)__cvta_generic_to_shared(&smk[0][r][c]);
        kAddrL[np] = (unsigned)__cvta_generic_to_shared(&smk[1][r][c]);
    }
    unsigned vAddrH[4], vAddrL[4];
#pragma unroll
    for (int dp = 0; dp < 4; dp++) {
        const int r = (lane & 15);
        const int c = dp * 16 + ((lane >> 4) & 1) * 8;
        vAddrH[dp] = (unsigned)__cvta_generic_to_shared(&smk[2][r][c]);
        vAddrL[dp] = (unsigned)__cvta_generic_to_shared(&smk[3][r][c]);
    }

    float o[8][4];
#pragma unroll
    for (int j = 0; j < 8; j++)
#pragma unroll
        for (int c = 0; c < 4; c++) o[j][c] = 0.f;
    float m_lo = -1e30f, m_hi = -1e30f, l_lo = 0.f, l_hi = 0.f;

    for (int jt = 0; jt < TT / AKV; jt++) {
        // Prefetch KV tile (4 matrices, 64x64 bf16 each)
        const __nv_bfloat16* srcs[4] = {
            Khp + (size_t)jt * AKV * DD, Klp + (size_t)jt * AKV * DD,
            Vhp + (size_t)jt * AKV * DD, Vlp + (size_t)jt * AKV * DD};
        uint4 pre[4][2];
#pragma unroll
        for (int mtx = 0; mtx < 4; mtx++)
#pragma unroll
            for (int i = 0; i < 2; i++) {
                const int lin = tid + i * 256;
                const int r = lin >> 3, c = (lin & 7) * 8;
                pre[mtx][i] = *(const uint4*)(srcs[mtx] + r * DD + c);
            }
        __syncthreads();
#pragma unroll
        for (int mtx = 0; mtx < 4; mtx++)
#pragma unroll
            for (int i = 0; i < 2; i++) {
                const int lin = tid + i * 256;
                const int r = lin >> 3, c = (lin & 7) * 8;
                *(uint4*)&smk[mtx][r][c] = pre[mtx][i];
            }
        __syncthreads();

        // ---- S = Q K^T (3-term split), raw scale ----
        float s[8][4];
#pragma unroll
        for (int j = 0; j < 8; j++)
#pragma unroll
            for (int c = 0; c < 4; c++) s[j][c] = 0.f;

#pragma unroll
        for (int kk = 0; kk < 4; kk++) {
            const unsigned koff = kk * 32;  // 16 bf16 cols
#pragma unroll
            for (int np = 0; np < 4; np++) {
                unsigned kh4[4], kl4[4];
                ldsm_x4(kh4, kAddrH[np] + koff);
                ldsm_x4(kl4, kAddrL[np] + koff);
                unsigned bhe[2] = {kh4[0], kh4[2]}, bho[2] = {kh4[1], kh4[3]};
                unsigned ble[2] = {kl4[0], kl4[2]}, blo[2] = {kl4[1], kl4[3]};
                mma_bf16(s[2 * np], qfh[kk], bhe);
                mma_bf16(s[2 * np], qfh[kk], ble);
                mma_bf16(s[2 * np], qfl[kk], bhe);
                mma_bf16(s[2 * np + 1], qfh[kk], bho);
                mma_bf16(s[2 * np + 1], qfh[kk], blo);
                mma_bf16(s[2 * np + 1], qfl[kk], bho);
            }
        }

        // ---- Online softmax on fragments (scale 1/8 folded into exp) ----
        float tml = -1e30f, tmh = -1e30f;
#pragma unroll
        for (int j = 0; j < 8; j++) {
            tml = fmaxf(tml, fmaxf(s[j][0], s[j][1]));
            tmh = fmaxf(tmh, fmaxf(s[j][2], s[j][3]));
        }
        tml = fmaxf(tml, __shfl_xor_sync(0xffffffff, tml, 1));
        tml = fmaxf(tml, __shfl_xor_sync(0xffffffff, tml, 2));
        tmh = fmaxf(tmh, __shfl_xor_sync(0xffffffff, tmh, 1));
        tmh = fmaxf(tmh, __shfl_xor_sync(0xffffffff, tmh, 2));

        const float mnl = fmaxf(m_lo, tml);
        const float mnh = fmaxf(m_hi, tmh);
        const float al = __expf((m_lo - mnl) * 0.125f);
        const float ah = __expf((m_hi - mnh) * 0.125f);
        m_lo = mnl; m_hi = mnh;
        const float cl = mnl * 0.125f, ch = mnh * 0.125f;

        float suml = 0.f, sumh = 0.f;
#pragma unroll
        for (int j = 0; j < 8; j++) {
            float p0 = __expf(fmaf(s[j][0], 0.125f, -cl));
            float p1 = __expf(fmaf(s[j][1], 0.125f, -cl));
            float p2 = __expf(fmaf(s[j][2], 0.125f, -ch));
            float p3 = __expf(fmaf(s[j][3], 0.125f, -ch));
            s[j][0] = p0; s[j][1] = p1; s[j][2] = p2; s[j][3] = p3;
            suml += p0 + p1; sumh += p2 + p3;
        }
        suml += __shfl_xor_sync(0xffffffff, suml, 1);
        suml += __shfl_xor_sync(0xffffffff, suml, 2);
        sumh += __shfl_xor_sync(0xffffffff, sumh, 1);
        sumh += __shfl_xor_sync(0xffffffff, sumh, 2);
        l_lo = l_lo * al + suml;
        l_hi = l_hi * ah + sumh;

#pragma unroll
        for (int j = 0; j < 8; j++) {
            o[j][0] *= al; o[j][1] *= al; o[j][2] *= ah; o[j][3] *= ah;
        }

        // ---- O += P V (3-term split), P frags built in-register ----
#pragma unroll
        for (int kk = 0; kk < 4; kk++) {
            unsigned ph[4], pl[4];
            float r0, r1;
            ph[0] = pack_hi(s[2 * kk][0], s[2 * kk][1], r0, r1);
            pl[0] = pack_lo(r0, r1);
            ph[1] = pack_hi(s[2 * kk][2], s[2 * kk][3], r0, r1);
            pl[1] = pack_lo(r0, r1);
            ph[2] = pack_hi(s[2 * kk + 1][0], s[2 * kk + 1][1], r0, r1);
            pl[2] = pack_lo(r0, r1);
            ph[3] = pack_hi(s[2 * kk + 1][2], s[2 * kk + 1][3], r0, r1);
            pl[3] = pack_lo(r0, r1);

            const unsigned roff = kk * 16 * SVLD * 2;  // 16 kv rows
#pragma unroll
            for (int dp = 0; dp < 4; dp++) {
                unsigned vh4[4], vl4[4];
                ldsm_x4t(vh4, vAddrH[dp] + roff);
                ldsm_x4t(vl4, vAddrL[dp] + roff);
                unsigned bhe[2] = {vh4[0], vh4[1]}, bho[2] = {vh4[2], vh4[3]};
                unsigned ble[2] = {vl4[0], vl4[1]}, blo[2] = {vl4[2], vl4[3]};
                mma_bf16(o[2 * dp], ph, bhe);
                mma_bf16(o[2 * dp], ph, ble);
                mma_bf16(o[2 * dp], pl, bhe);
                mma_bf16(o[2 * dp + 1], ph, bho);
                mma_bf16(o[2 * dp + 1], ph, blo);
                mma_bf16(o[2 * dp + 1], pl, bho);
            }
        }
    }

    // ---- Epilogue: normalize, split to bf16, write (b,t,h,d) ----
    const int b = bh >> 4;
    const int h = bh & 15;
    const float invl = 1.f / l_lo;
    const float invh = 1.f / l_hi;
    const int t_lo = q0 + wid * 16 + (lane >> 2);
    const int t_hi = t_lo + 8;

#pragma unroll
    for (int j = 0; j < 8; j++) {
        const int d = j * 8 + (lane & 3) * 2;
        {
            const size_t idx = ((size_t)(b * TT + t_lo) * HH + h) * DD + d;
            float vx = o[j][0] * invl, vy = o[j][1] * invl;
            __nv_bfloat162 hh = __float22bfloat162_rn(make_float2(vx, vy));
            float2 hf = __bfloat1622float2(hh);
            __nv_bfloat162 ll = __float22bfloat162_rn(make_float2(vx - hf.x, vy - hf.y));
            *(__nv_bfloat162*)&g_chi[idx] = hh;
            *(__nv_bfloat162*)&g_clo[idx] = ll;
        }
        {
            const size_t idx = ((size_t)(b * TT + t_hi) * HH + h) * DD + d;
            float vx = o[j][2] * invh, vy = o[j][3] * invh;
            __nv_bfloat162 hh = __float22bfloat162_rn(make_float2(vx, vy));
            float2 hf = __bfloat1622float2(hh);
            __nv_bfloat162 ll = __float22bfloat162_rn(make_float2(vx - hf.x, vy - hf.y));
            *(__nv_bfloat162*)&g_chi[idx] = hh;
            *(__nv_bfloat162*)&g_clo[idx] = ll;
        }
    }
}

// ---------------------------------------------------------------------------
// Launch
// ---------------------------------------------------------------------------
extern "C" void kernel_launch(void* const* d_in, const int* in_sizes, int n_in,
                              void* d_out, int out_size)
{
    const float* x  = (const float*)d_in[0];
    const float* Wq = (const float*)d_in[1];
    const float* bq = (const float*)d_in[2];
    const float* Wk = (const float*)d_in[3];
    const float* bk = (const float*)d_in[4];
    const float* Wv = (const float*)d_in[5];
    const float* bv = (const float*)d_in[6];
    const float* Wo = (const float*)d_in[7];
    const float* bo = (const float*)d_in[8];
    float* out = (float*)d_out;

    __nv_bfloat16 *xhi, *xlo, *whi, *wlo, *chi, *clo;
    __nv_bfloat16 *qh, *ql, *kh, *kl, *vh, *vl;
    cudaGetSymbolAddress((void**)&xhi, g_xhi);
    cudaGetSymbolAddress((void**)&xlo, g_xlo);
    cudaGetSymbolAddress((void**)&whi, g_whi);
    cudaGetSymbolAddress((void**)&wlo, g_wlo);
    cudaGetSymbolAddress((void**)&chi, g_chi);
    cudaGetSymbolAddress((void**)&clo, g_clo);
    cudaGetSymbolAddress((void**)&qh, g_qh);
    cudaGetSymbolAddress((void**)&ql, g_ql);
    cudaGetSymbolAddress((void**)&kh, g_kh);
    cudaGetSymbolAddress((void**)&kl, g_kl);
    cudaGetSymbolAddress((void**)&vh, g_vh);
    cudaGetSymbolAddress((void**)&vl, g_vl);

    const int n4x = (int)((size_t)MM * NU / 4);
    split_convert<<<(n4x + 255) / 256, 256>>>((const float4*)x, (uint2*)xhi,
                                              (uint2*)xlo, n4x);
    const int n4w = NU * NU / 4;
    const float* Ws[4] = {Wq, Wk, Wv, Wo};
    for (int w = 0; w < 4; w++) {
        split_convert<<<(n4w + 255) / 256, 256>>>(
            (const float4*)Ws[w],
            (uint2*)(whi + (size_t)w * NU * NU),
            (uint2*)(wlo + (size_t)w * NU * NU), n4w);
    }

    const dim3 gGemm(NU / GBN, MM / GBM);  // (8, 64)

    gemm_bf16_split<<<gGemm, 256>>>(xhi, xlo, whi, wlo, bq, nullptr, qh, ql, 1);
    gemm_bf16_split<<<gGemm, 256>>>(xhi, xlo, whi + (size_t)NU * NU,
                                    wlo + (size_t)NU * NU, bk, nullptr, kh, kl, 1);
    gemm_bf16_split<<<gGemm, 256>>>(xhi, xlo, whi + 2 * (size_t)NU * NU,
                                    wlo + 2 * (size_t)NU * NU, bv, nullptr, vh, vl, 1);

    attn_tc<<<dim3(TT / ATQ, BB * HH), 256>>>();

    gemm_bf16_split<<<gGemm, 256>>>(chi, clo, whi + 3 * (size_t)NU * NU,
                                    wlo + 3 * (size_t)NU * NU, bo, out, nullptr,
                                    nullptr, 0);
}

// round 9
// speedup vs baseline: 3.2382x; 1.2505x over previous
#include <cuda_runtime.h>
#include <cuda_bf16.h>
#include <math.h>

// Problem constants
#define BB 4
#define TT 2048
#define HH 16
#define DD 64
#define NU 1024
#define MM (BB * TT)  // 8192

// Scratch (device globals: allocation-free)
__device__ __nv_bfloat16 g_xhi[(size_t)MM * NU];
__device__ __nv_bfloat16 g_xlo[(size_t)MM * NU];
__device__ __nv_bfloat16 g_whi[4 * (size_t)NU * NU];
__device__ __nv_bfloat16 g_wlo[4 * (size_t)NU * NU];
__device__ __nv_bfloat16 g_qh[(size_t)MM * NU];
__device__ __nv_bfloat16 g_ql[(size_t)MM * NU];
__device__ __nv_bfloat16 g_kh[(size_t)MM * NU];
__device__ __nv_bfloat16 g_kl[(size_t)MM * NU];
__device__ __nv_bfloat16 g_vh[(size_t)MM * NU];
__device__ __nv_bfloat16 g_vl[(size_t)MM * NU];
__device__ __nv_bfloat16 g_chi[(size_t)MM * NU];
__device__ __nv_bfloat16 g_clo[(size_t)MM * NU];

// ---------------------------------------------------------------------------
// Split fp32 -> bf16 hi + bf16 lo
// ---------------------------------------------------------------------------
__global__ __launch_bounds__(256) void split_convert(
    const float4* __restrict__ in, uint2* __restrict__ hi,
    uint2* __restrict__ lo, int n4)
{
    int i = blockIdx.x * blockDim.x + threadIdx.x;
    if (i >= n4) return;
    float4 v = in[i];
    __nv_bfloat16 h0 = __float2bfloat16_rn(v.x);
    __nv_bfloat16 h1 = __float2bfloat16_rn(v.y);
    __nv_bfloat16 h2 = __float2bfloat16_rn(v.z);
    __nv_bfloat16 h3 = __float2bfloat16_rn(v.w);
    __nv_bfloat16 l0 = __float2bfloat16_rn(v.x - __bfloat162float(h0));
    __nv_bfloat16 l1 = __float2bfloat16_rn(v.y - __bfloat162float(h1));
    __nv_bfloat16 l2 = __float2bfloat16_rn(v.z - __bfloat162float(h2));
    __nv_bfloat16 l3 = __float2bfloat16_rn(v.w - __bfloat162float(h3));
    union { __nv_bfloat16 b[4]; uint2 u; } ph, pl;
    ph.b[0] = h0; ph.b[1] = h1; ph.b[2] = h2; ph.b[3] = h3;
    pl.b[0] = l0; pl.b[1] = l1; pl.b[2] = l2; pl.b[3] = l3;
    hi[i] = ph.u;
    lo[i] = pl.u;
}

// ---------------------------------------------------------------------------
// Helpers
// ---------------------------------------------------------------------------
__device__ __forceinline__ unsigned smem_u32(const void* p)
{
    return (unsigned)__cvta_generic_to_shared(p);
}

__device__ __forceinline__ void mma_bf16(float* d, const unsigned* a, const unsigned* b)
{
    asm volatile(
        "mma.sync.aligned.m16n8k16.row.col.f32.bf16.bf16.f32 "
        "{%0,%1,%2,%3}, {%4,%5,%6,%7}, {%8,%9}, {%0,%1,%2,%3};\n"
        : "+f"(d[0]), "+f"(d[1]), "+f"(d[2]), "+f"(d[3])
        : "r"(a[0]), "r"(a[1]), "r"(a[2]), "r"(a[3]), "r"(b[0]), "r"(b[1]));
}

__device__ __forceinline__ void ldsm_x4(unsigned* r, unsigned addr)
{
    asm volatile("ldmatrix.sync.aligned.m8n8.x4.shared.b16 {%0,%1,%2,%3}, [%4];\n"
                 : "=r"(r[0]), "=r"(r[1]), "=r"(r[2]), "=r"(r[3]) : "r"(addr));
}

__device__ __forceinline__ void ldsm_x2(unsigned* r, unsigned addr)
{
    asm volatile("ldmatrix.sync.aligned.m8n8.x2.shared.b16 {%0,%1}, [%2];\n"
                 : "=r"(r[0]), "=r"(r[1]) : "r"(addr));
}

__device__ __forceinline__ void ldsm_x4t(unsigned* r, unsigned addr)
{
    asm volatile("ldmatrix.sync.aligned.m8n8.x4.trans.shared.b16 {%0,%1,%2,%3}, [%4];\n"
                 : "=r"(r[0]), "=r"(r[1]), "=r"(r[2]), "=r"(r[3]) : "r"(addr));
}

__device__ __forceinline__ unsigned pack_hi(float a, float b, float& ra, float& rb)
{
    __nv_bfloat162 h = __float22bfloat162_rn(make_float2(a, b));
    float2 hf = __bfloat1622float2(h);
    ra = a - hf.x;
    rb = b - hf.y;
    return *(unsigned*)&h;
}

__device__ __forceinline__ unsigned pack_lo(float a, float b)
{
    __nv_bfloat162 h = __float22bfloat162_rn(make_float2(a, b));
    return *(unsigned*)&h;
}

__device__ __forceinline__ void cp_async16(unsigned saddr, const void* gaddr)
{
    asm volatile("cp.async.cg.shared.global [%0], [%1], 16;\n"
                 :: "r"(saddr), "l"(gaddr));
}

#define CP_COMMIT() asm volatile("cp.async.commit_group;\n" ::: "memory")
#define CP_WAIT1()  asm volatile("cp.async.wait_group 1;\n" ::: "memory")

// ---------------------------------------------------------------------------
// Split-bf16 tensor-core GEMM (NT), 2-stage cp.async pipeline.
// C = A @ W^T + bias.  Tile 128x128, K-chunk 32, 256 threads = 8 warps.
// mode 0: fp32 C[m*1024+n];  mode 1: split bf16 head-split layout.
// ---------------------------------------------------------------------------
#define GKC 32
#define GLD 40                       // smem row stride in bf16 (80B)
#define G_MTX_B (128 * GLD * 2)      // bytes per matrix per stage (10240)
#define G_STG_B (4 * G_MTX_B)        // bytes per stage (40960)
#define G_SMEM_TOTAL (2 * G_STG_B)   // 81920

__global__ __launch_bounds__(256) void gemm_bf16_split(
    const __nv_bfloat16* __restrict__ Ahi, const __nv_bfloat16* __restrict__ Alo,
    const __nv_bfloat16* __restrict__ Bhi, const __nv_bfloat16* __restrict__ Blo,
    const float* __restrict__ bias, float* __restrict__ C,
    __nv_bfloat16* __restrict__ Chi, __nv_bfloat16* __restrict__ Clo, int mode)
{
    extern __shared__ __align__(128) char smG[];
    const unsigned sbase = smem_u32(smG);

    const int tid = threadIdx.x;
    const int wid = tid >> 5;
    const int lane = tid & 31;
    const int wm = wid >> 2;
    const int wn = wid & 3;
    const int rowBase = blockIdx.y * 128;
    const int colBase = blockIdx.x * 128;

    // Loader mapping: 2048 x 16B per stage, 8 per thread.
    // lin = tid + i*256; mtx = lin>>9; rem = lin&511; row = rem>>2; ch = rem&3
    const __nv_bfloat16* gsrc[4] = {
        Ahi + (size_t)rowBase * NU, Alo + (size_t)rowBase * NU,
        Bhi + (size_t)colBase * NU, Blo + (size_t)colBase * NU};

    // ldmatrix base addresses (stage 0)
    unsigned aAddrH[4], aAddrL[4], bAddrH[4], bAddrL[4];
#pragma unroll
    for (int mt = 0; mt < 4; mt++) {
        const int r = wm * 64 + mt * 16 + (lane & 15);
        const int c = ((lane >> 4) & 1) * 8;
        aAddrH[mt] = sbase + 0 * G_MTX_B + (r * GLD + c) * 2;
        aAddrL[mt] = sbase + 1 * G_MTX_B + (r * GLD + c) * 2;
    }
#pragma unroll
    for (int nt = 0; nt < 4; nt++) {
        const int r = wn * 32 + nt * 8 + (lane & 7);
        const int c = ((lane >> 3) & 1) * 8;
        bAddrH[nt] = sbase + 2 * G_MTX_B + (r * GLD + c) * 2;
        bAddrL[nt] = sbase + 3 * G_MTX_B + (r * GLD + c) * 2;
    }

    float acc[4][4][4];
#pragma unroll
    for (int i = 0; i < 4; i++)
#pragma unroll
        for (int j = 0; j < 4; j++)
#pragma unroll
            for (int c = 0; c < 4; c++) acc[i][j][c] = 0.f;

    // async stage loader
    auto load_stage = [&](int st, int chunk) {
        const int k0 = chunk * GKC;
        const unsigned stb = sbase + st * G_STG_B;
#pragma unroll
        for (int i = 0; i < 8; i++) {
            const int lin = tid + i * 256;
            const int mtx = lin >> 9;
            const int rem = lin & 511;
            const int row = rem >> 2;
            const int ch = rem & 3;
            cp_async16(stb + mtx * G_MTX_B + (row * GLD + ch * 8) * 2,
                       gsrc[mtx] + (size_t)row * NU + k0 + ch * 8);
        }
    };

    const int NCHUNK = NU / GKC;  // 32
    load_stage(0, 0); CP_COMMIT();
    load_stage(1, 1); CP_COMMIT();

    for (int chunk = 0; chunk < NCHUNK; chunk++) {
        const int st = chunk & 1;
        const unsigned stoff = st * G_STG_B;
        CP_WAIT1();
        __syncthreads();

#pragma unroll
        for (int ks = 0; ks < 2; ks++) {
            const unsigned koff = stoff + ks * 32;  // 16 bf16 cols
            unsigned bh[4][2], bl[4][2];
#pragma unroll
            for (int nt = 0; nt < 4; nt++) {
                ldsm_x2(bh[nt], bAddrH[nt] + koff);
                ldsm_x2(bl[nt], bAddrL[nt] + koff);
            }
#pragma unroll
            for (int mt = 0; mt < 4; mt++) {
                unsigned ah[4], al[4];
                ldsm_x4(ah, aAddrH[mt] + koff);
                ldsm_x4(al, aAddrL[mt] + koff);
#pragma unroll
                for (int nt = 0; nt < 4; nt++) mma_bf16(acc[mt][nt], ah, bh[nt]);
#pragma unroll
                for (int nt = 0; nt < 4; nt++) mma_bf16(acc[mt][nt], ah, bl[nt]);
#pragma unroll
                for (int nt = 0; nt < 4; nt++) mma_bf16(acc[mt][nt], al, bh[nt]);
            }
        }

        __syncthreads();
        if (chunk + 2 < NCHUNK) load_stage(st, chunk + 2);
        CP_COMMIT();
    }

    // Epilogue
#pragma unroll
    for (int mt = 0; mt < 4; mt++) {
#pragma unroll
        for (int nt = 0; nt < 4; nt++) {
            const int m = rowBase + wm * 64 + mt * 16 + (lane >> 2);
            const int n = colBase + wn * 32 + nt * 8 + (lane & 3) * 2;
            const float b0 = bias[n];
            const float b1 = bias[n + 1];
            float v0x = acc[mt][nt][0] + b0, v0y = acc[mt][nt][1] + b1;
            float v1x = acc[mt][nt][2] + b0, v1y = acc[mt][nt][3] + b1;
            if (mode == 0) {
                *(float2*)&C[(size_t)m * NU + n] = make_float2(v0x, v0y);
                *(float2*)&C[(size_t)(m + 8) * NU + n] = make_float2(v1x, v1y);
            } else {
                const int h = n >> 6, d = n & 63;
#pragma unroll
                for (int rr = 0; rr < 2; rr++) {
                    const int mr = m + rr * 8;
                    const int b = mr >> 11, t = mr & 2047;
                    const size_t idx = (((size_t)(b * HH + h) * TT) + t) * DD + d;
                    float vx = rr ? v1x : v0x, vy = rr ? v1y : v0y;
                    __nv_bfloat162 hh = __float22bfloat162_rn(make_float2(vx, vy));
                    float2 hf = __bfloat1622float2(hh);
                    __nv_bfloat162 ll = __float22bfloat162_rn(
                        make_float2(vx - hf.x, vy - hf.y));
                    *(__nv_bfloat162*)&Chi[idx] = hh;
                    *(__nv_bfloat162*)&Clo[idx] = ll;
                }
            }
        }
    }
}

// ---------------------------------------------------------------------------
// Tensor-core flash attention, split-bf16, 2-stage cp.async KV pipeline.
// Grid: (T/128, B*H). 256 threads = 8 warps; warp owns 16 query rows.
// ---------------------------------------------------------------------------
#define ATQ 128
#define AKV 64
#define SVLD 72                       // row stride bf16 (144B)
#define A_MTX_B (AKV * SVLD * 2)      // 9216 bytes per matrix
#define A_STG_B (4 * A_MTX_B)         // 36864 per stage
#define A_SMEM_TOTAL (2 * A_STG_B)    // 73728

__global__ __launch_bounds__(256) void attn_tc()
{
    extern __shared__ __align__(128) char smA[];
    const unsigned sbase = smem_u32(smA);
    __nv_bfloat16* smk = (__nv_bfloat16*)smA;

    const int tid = threadIdx.x;
    const int lane = tid & 31;
    const int wid = tid >> 5;
    const int bh = blockIdx.y;
    const int q0 = blockIdx.x * ATQ;

    const size_t kvbase = (size_t)bh * TT * DD;
    const __nv_bfloat16* Qhp = g_qh + kvbase + (size_t)q0 * DD;
    const __nv_bfloat16* Qlp = g_ql + kvbase + (size_t)q0 * DD;
    const __nv_bfloat16* gsrc[4] = {g_kh + kvbase, g_kl + kvbase,
                                    g_vh + kvbase, g_vl + kvbase};

    // ---- Stage Q (128x64 hi/lo) into stage-0 smem, pull frags to regs ----
    __nv_bfloat16* sQh = smk;                      // matrix slot 0
    __nv_bfloat16* sQl = smk + 2 * AKV * SVLD;     // matrix slot 2
    {
        const int r = tid >> 1;
        const int c = (tid & 1) * 32;
        const uint4* gh = (const uint4*)(Qhp + (size_t)r * DD + c);
        const uint4* gl = (const uint4*)(Qlp + (size_t)r * DD + c);
        // rows 0..127 at stride SVLD/2 fits inside slots 0+1 region; use
        // direct addressing across the whole stage-0 buffer (128 rows).
        uint4* dh = (uint4*)(sQh + r * SVLD + c);
        uint4* dl = (uint4*)(sQl + r * SVLD + c);
#pragma unroll
        for (int i = 0; i < 4; i++) { dh[i] = gh[i]; dl[i] = gl[i]; }
    }
    __syncthreads();

    unsigned qfh[4][4], qfl[4][4];
    {
        const int qrow = wid * 16 + (lane & 15);
        const int ccol = ((lane >> 4) & 1) * 8;
#pragma unroll
        for (int kk = 0; kk < 4; kk++) {
            ldsm_x4(qfh[kk], smem_u32(sQh + qrow * SVLD + kk * 16 + ccol));
            ldsm_x4(qfl[kk], smem_u32(sQl + qrow * SVLD + kk * 16 + ccol));
        }
    }
    __syncthreads();

    // ldmatrix base addresses (stage 0): K slots 0,1 ; V slots 2,3
    unsigned kAddrH[4], kAddrL[4];
#pragma unroll
    for (int np = 0; np < 4; np++) {
        const int r = np * 16 + (lane & 15);
        const int c = ((lane >> 4) & 1) * 8;
        kAddrH[np] = sbase + 0 * A_MTX_B + (r * SVLD + c) * 2;
        kAddrL[np] = sbase + 1 * A_MTX_B + (r * SVLD + c) * 2;
    }
    unsigned vAddrH[4], vAddrL[4];
#pragma unroll
    for (int dp = 0; dp < 4; dp++) {
        const int r = (lane & 15);
        const int c = dp * 16 + ((lane >> 4) & 1) * 8;
        vAddrH[dp] = sbase + 2 * A_MTX_B + (r * SVLD + c) * 2;
        vAddrL[dp] = sbase + 3 * A_MTX_B + (r * SVLD + c) * 2;
    }

    // async KV tile loader: 4 matrices x 64 rows x 8 chunks = 2048 x16B
    auto load_tile = [&](int st, int jt) {
        const unsigned stb = sbase + st * A_STG_B;
        const size_t goff = (size_t)jt * AKV * DD;
#pragma unroll
        for (int i = 0; i < 8; i++) {
            const int lin = tid + i * 256;
            const int mtx = lin >> 9;
            const int rem = lin & 511;
            const int row = rem >> 3;
            const int ch = rem & 7;
            cp_async16(stb + mtx * A_MTX_B + (row * SVLD + ch * 8) * 2,
                       gsrc[mtx] + goff + row * DD + ch * 8);
        }
    };

    float o[8][4];
#pragma unroll
    for (int j = 0; j < 8; j++)
#pragma unroll
        for (int c = 0; c < 4; c++) o[j][c] = 0.f;
    float m_lo = -1e30f, m_hi = -1e30f, l_lo = 0.f, l_hi = 0.f;

    const int NT = TT / AKV;  // 32
    load_tile(0, 0); CP_COMMIT();
    load_tile(1, 1); CP_COMMIT();

    for (int jt = 0; jt < NT; jt++) {
        const int st = jt & 1;
        const unsigned stoff = st * A_STG_B;
        CP_WAIT1();
        __syncthreads();

        // ---- S = Q K^T (3-term split) ----
        float s[8][4];
#pragma unroll
        for (int j = 0; j < 8; j++)
#pragma unroll
            for (int c = 0; c < 4; c++) s[j][c] = 0.f;

#pragma unroll
        for (int kk = 0; kk < 4; kk++) {
            const unsigned koff = stoff + kk * 32;
#pragma unroll
            for (int np = 0; np < 4; np++) {
                unsigned kh4[4], kl4[4];
                ldsm_x4(kh4, kAddrH[np] + koff);
                ldsm_x4(kl4, kAddrL[np] + koff);
                unsigned bhe[2] = {kh4[0], kh4[2]}, bho[2] = {kh4[1], kh4[3]};
                unsigned ble[2] = {kl4[0], kl4[2]}, blo[2] = {kl4[1], kl4[3]};
                mma_bf16(s[2 * np], qfh[kk], bhe);
                mma_bf16(s[2 * np], qfh[kk], ble);
                mma_bf16(s[2 * np], qfl[kk], bhe);
                mma_bf16(s[2 * np + 1], qfh[kk], bho);
                mma_bf16(s[2 * np + 1], qfh[kk], blo);
                mma_bf16(s[2 * np + 1], qfl[kk], bho);
            }
        }

        // ---- Online softmax on fragments ----
        float tml = -1e30f, tmh = -1e30f;
#pragma unroll
        for (int j = 0; j < 8; j++) {
            tml = fmaxf(tml, fmaxf(s[j][0], s[j][1]));
            tmh = fmaxf(tmh, fmaxf(s[j][2], s[j][3]));
        }
        tml = fmaxf(tml, __shfl_xor_sync(0xffffffff, tml, 1));
        tml = fmaxf(tml, __shfl_xor_sync(0xffffffff, tml, 2));
        tmh = fmaxf(tmh, __shfl_xor_sync(0xffffffff, tmh, 1));
        tmh = fmaxf(tmh, __shfl_xor_sync(0xffffffff, tmh, 2));

        const float mnl = fmaxf(m_lo, tml);
        const float mnh = fmaxf(m_hi, tmh);
        const float al = __expf((m_lo - mnl) * 0.125f);
        const float ah = __expf((m_hi - mnh) * 0.125f);
        m_lo = mnl; m_hi = mnh;
        const float cl = mnl * 0.125f, ch = mnh * 0.125f;

        float suml = 0.f, sumh = 0.f;
#pragma unroll
        for (int j = 0; j < 8; j++) {
            float p0 = __expf(fmaf(s[j][0], 0.125f, -cl));
            float p1 = __expf(fmaf(s[j][1], 0.125f, -cl));
            float p2 = __expf(fmaf(s[j][2], 0.125f, -ch));
            float p3 = __expf(fmaf(s[j][3], 0.125f, -ch));
            s[j][0] = p0; s[j][1] = p1; s[j][2] = p2; s[j][3] = p3;
            suml += p0 + p1; sumh += p2 + p3;
        }
        suml += __shfl_xor_sync(0xffffffff, suml, 1);
        suml += __shfl_xor_sync(0xffffffff, suml, 2);
        sumh += __shfl_xor_sync(0xffffffff, sumh, 1);
        sumh += __shfl_xor_sync(0xffffffff, sumh, 2);
        l_lo = l_lo * al + suml;
        l_hi = l_hi * ah + sumh;

#pragma unroll
        for (int j = 0; j < 8; j++) {
            o[j][0] *= al; o[j][1] *= al; o[j][2] *= ah; o[j][3] *= ah;
        }

        // ---- O += P V (3-term split) ----
#pragma unroll
        for (int kk = 0; kk < 4; kk++) {
            unsigned ph[4], pl[4];
            float r0, r1;
            ph[0] = pack_hi(s[2 * kk][0], s[2 * kk][1], r0, r1);
            pl[0] = pack_lo(r0, r1);
            ph[1] = pack_hi(s[2 * kk][2], s[2 * kk][3], r0, r1);
            pl[1] = pack_lo(r0, r1);
            ph[2] = pack_hi(s[2 * kk + 1][0], s[2 * kk + 1][1], r0, r1);
            pl[2] = pack_lo(r0, r1);
            ph[3] = pack_hi(s[2 * kk + 1][2], s[2 * kk + 1][3], r0, r1);
            pl[3] = pack_lo(r0, r1);

            const unsigned roff = stoff + kk * 16 * SVLD * 2;
#pragma unroll
            for (int dp = 0; dp < 4; dp++) {
                unsigned vh4[4], vl4[4];
                ldsm_x4t(vh4, vAddrH[dp] + roff);
                ldsm_x4t(vl4, vAddrL[dp] + roff);
                unsigned bhe[2] = {vh4[0], vh4[1]}, bho[2] = {vh4[2], vh4[3]};
                unsigned ble[2] = {vl4[0], vl4[1]}, blo[2] = {vl4[2], vl4[3]};
                mma_bf16(o[2 * dp], ph, bhe);
                mma_bf16(o[2 * dp], ph, ble);
                mma_bf16(o[2 * dp], pl, bhe);
                mma_bf16(o[2 * dp + 1], ph, bho);
                mma_bf16(o[2 * dp + 1], ph, blo);
                mma_bf16(o[2 * dp + 1], pl, bho);
            }
        }

        __syncthreads();
        if (jt + 2 < NT) load_tile(st, jt + 2);
        CP_COMMIT();
    }

    // ---- Epilogue: normalize, split to bf16, write (b,t,h,d) ----
    const int b = bh >> 4;
    const int h = bh & 15;
    const float invl = 1.f / l_lo;
    const float invh = 1.f / l_hi;
    const int t_lo = q0 + wid * 16 + (lane >> 2);
    const int t_hi = t_lo + 8;

#pragma unroll
    for (int j = 0; j < 8; j++) {
        const int d = j * 8 + (lane & 3) * 2;
        {
            const size_t idx = ((size_t)(b * TT + t_lo) * HH + h) * DD + d;
            float vx = o[j][0] * invl, vy = o[j][1] * invl;
            __nv_bfloat162 hh = __float22bfloat162_rn(make_float2(vx, vy));
            float2 hf = __bfloat1622float2(hh);
            __nv_bfloat162 ll = __float22bfloat162_rn(make_float2(vx - hf.x, vy - hf.y));
            *(__nv_bfloat162*)&g_chi[idx] = hh;
            *(__nv_bfloat162*)&g_clo[idx] = ll;
        }
        {
            const size_t idx = ((size_t)(b * TT + t_hi) * HH + h) * DD + d;
            float vx = o[j][2] * invh, vy = o[j][3] * invh;
            __nv_bfloat162 hh = __float22bfloat162_rn(make_float2(vx, vy));
            float2 hf = __bfloat1622float2(hh);
            __nv_bfloat162 ll = __float22bfloat162_rn(make_float2(vx - hf.x, vy - hf.y));
            *(__nv_bfloat162*)&g_chi[idx] = hh;
            *(__nv_bfloat162*)&g_clo[idx] = ll;
        }
    }
}

// ---------------------------------------------------------------------------
// Launch
// ---------------------------------------------------------------------------
extern "C" void kernel_launch(void* const* d_in, const int* in_sizes, int n_in,
                              void* d_out, int out_size)
{
    const float* x  = (const float*)d_in[0];
    const float* Wq = (const float*)d_in[1];
    const float* bq = (const float*)d_in[2];
    const float* Wk = (const float*)d_in[3];
    const float* bk = (const float*)d_in[4];
    const float* Wv = (const float*)d_in[5];
    const float* bv = (const float*)d_in[6];
    const float* Wo = (const float*)d_in[7];
    const float* bo = (const float*)d_in[8];
    float* out = (float*)d_out;

    __nv_bfloat16 *xhi, *xlo, *whi, *wlo, *chi, *clo;
    __nv_bfloat16 *qh, *ql, *kh, *kl, *vh, *vl;
    cudaGetSymbolAddress((void**)&xhi, g_xhi);
    cudaGetSymbolAddress((void**)&xlo, g_xlo);
    cudaGetSymbolAddress((void**)&whi, g_whi);
    cudaGetSymbolAddress((void**)&wlo, g_wlo);
    cudaGetSymbolAddress((void**)&chi, g_chi);
    cudaGetSymbolAddress((void**)&clo, g_clo);
    cudaGetSymbolAddress((void**)&qh, g_qh);
    cudaGetSymbolAddress((void**)&ql, g_ql);
    cudaGetSymbolAddress((void**)&kh, g_kh);
    cudaGetSymbolAddress((void**)&kl, g_kl);
    cudaGetSymbolAddress((void**)&vh, g_vh);
    cudaGetSymbolAddress((void**)&vl, g_vl);

    const int n4x = (int)((size_t)MM * NU / 4);
    split_convert<<<(n4x + 255) / 256, 256>>>((const float4*)x, (uint2*)xhi,
                                              (uint2*)xlo, n4x);
    const int n4w = NU * NU / 4;
    const float* Ws[4] = {Wq, Wk, Wv, Wo};
    for (int w = 0; w < 4; w++) {
        split_convert<<<(n4w + 255) / 256, 256>>>(
            (const float4*)Ws[w],
            (uint2*)(whi + (size_t)w * NU * NU),
            (uint2*)(wlo + (size_t)w * NU * NU), n4w);
    }

    cudaFuncSetAttribute(gemm_bf16_split,
                         cudaFuncAttributeMaxDynamicSharedMemorySize,
                         G_SMEM_TOTAL);
    cudaFuncSetAttribute(attn_tc,
                         cudaFuncAttributeMaxDynamicSharedMemorySize,
                         A_SMEM_TOTAL);

    const dim3 gGemm(NU / 128, MM / 128);  // (8, 64)

    gemm_bf16_split<<<gGemm, 256, G_SMEM_TOTAL>>>(
        xhi, xlo, whi, wlo, bq, nullptr, qh, ql, 1);
    gemm_bf16_split<<<gGemm, 256, G_SMEM_TOTAL>>>(
        xhi, xlo, whi + (size_t)NU * NU, wlo + (size_t)NU * NU, bk, nullptr,
        kh, kl, 1);
    gemm_bf16_split<<<gGemm, 256, G_SMEM_TOTAL>>>(
        xhi, xlo, whi + 2 * (size_t)NU * NU, wlo + 2 * (size_t)NU * NU, bv,
        nullptr, vh, vl, 1);

    attn_tc<<<dim3(TT / ATQ, BB * HH), 256, A_SMEM_TOTAL>>>();

    gemm_bf16_split<<<gGemm, 256, G_SMEM_TOTAL>>>(
        chi, clo, whi + 3 * (size_t)NU * NU, wlo + 3 * (size_t)NU * NU, bo, out,
        nullptr, nullptr, 0);
}

// round 10
// speedup vs baseline: 4.4937x; 1.3877x over previous
#include <cuda_runtime.h>
#include <cuda_bf16.h>
#include <cuda_fp16.h>
#include <math.h>

// Problem constants
#define BB 4
#define TT 2048
#define HH 16
#define DD 64
#define NU 1024
#define MM (BB * TT)  // 8192

// Scratch (device globals: allocation-free)
__device__ __nv_bfloat16 g_xhi[(size_t)MM * NU];
__device__ __nv_bfloat16 g_xlo[(size_t)MM * NU];
__device__ __nv_bfloat16 g_whi[4 * (size_t)NU * NU];
__device__ __nv_bfloat16 g_wlo[4 * (size_t)NU * NU];
__device__ __half g_q16[(size_t)MM * NU];
__device__ __half g_k16[(size_t)MM * NU];
__device__ __half g_v16[(size_t)MM * NU];
__device__ __nv_bfloat16 g_chi[(size_t)MM * NU];
__device__ __nv_bfloat16 g_clo[(size_t)MM * NU];

// ---------------------------------------------------------------------------
// Split fp32 -> bf16 hi + bf16 lo
// ---------------------------------------------------------------------------
__global__ __launch_bounds__(256) void split_convert(
    const float4* __restrict__ in, uint2* __restrict__ hi,
    uint2* __restrict__ lo, int n4)
{
    int i = blockIdx.x * blockDim.x + threadIdx.x;
    if (i >= n4) return;
    float4 v = in[i];
    __nv_bfloat16 h0 = __float2bfloat16_rn(v.x);
    __nv_bfloat16 h1 = __float2bfloat16_rn(v.y);
    __nv_bfloat16 h2 = __float2bfloat16_rn(v.z);
    __nv_bfloat16 h3 = __float2bfloat16_rn(v.w);
    __nv_bfloat16 l0 = __float2bfloat16_rn(v.x - __bfloat162float(h0));
    __nv_bfloat16 l1 = __float2bfloat16_rn(v.y - __bfloat162float(h1));
    __nv_bfloat16 l2 = __float2bfloat16_rn(v.z - __bfloat162float(h2));
    __nv_bfloat16 l3 = __float2bfloat16_rn(v.w - __bfloat162float(h3));
    union { __nv_bfloat16 b[4]; uint2 u; } ph, pl;
    ph.b[0] = h0; ph.b[1] = h1; ph.b[2] = h2; ph.b[3] = h3;
    pl.b[0] = l0; pl.b[1] = l1; pl.b[2] = l2; pl.b[3] = l3;
    hi[i] = ph.u;
    lo[i] = pl.u;
}

// ---------------------------------------------------------------------------
// Helpers
// ---------------------------------------------------------------------------
__device__ __forceinline__ unsigned smem_u32(const void* p)
{
    return (unsigned)__cvta_generic_to_shared(p);
}

__device__ __forceinline__ void mma_bf16(float* d, const unsigned* a, const unsigned* b)
{
    asm volatile(
        "mma.sync.aligned.m16n8k16.row.col.f32.bf16.bf16.f32 "
        "{%0,%1,%2,%3}, {%4,%5,%6,%7}, {%8,%9}, {%0,%1,%2,%3};\n"
        : "+f"(d[0]), "+f"(d[1]), "+f"(d[2]), "+f"(d[3])
        : "r"(a[0]), "r"(a[1]), "r"(a[2]), "r"(a[3]), "r"(b[0]), "r"(b[1]));
}

__device__ __forceinline__ void mma_f16(float* d, const unsigned* a, const unsigned* b)
{
    asm volatile(
        "mma.sync.aligned.m16n8k16.row.col.f32.f16.f16.f32 "
        "{%0,%1,%2,%3}, {%4,%5,%6,%7}, {%8,%9}, {%0,%1,%2,%3};\n"
        : "+f"(d[0]), "+f"(d[1]), "+f"(d[2]), "+f"(d[3])
        : "r"(a[0]), "r"(a[1]), "r"(a[2]), "r"(a[3]), "r"(b[0]), "r"(b[1]));
}

__device__ __forceinline__ void ldsm_x4(unsigned* r, unsigned addr)
{
    asm volatile("ldmatrix.sync.aligned.m8n8.x4.shared.b16 {%0,%1,%2,%3}, [%4];\n"
                 : "=r"(r[0]), "=r"(r[1]), "=r"(r[2]), "=r"(r[3]) : "r"(addr));
}

__device__ __forceinline__ void ldsm_x2(unsigned* r, unsigned addr)
{
    asm volatile("ldmatrix.sync.aligned.m8n8.x2.shared.b16 {%0,%1}, [%2];\n"
                 : "=r"(r[0]), "=r"(r[1]) : "r"(addr));
}

__device__ __forceinline__ void ldsm_x4t(unsigned* r, unsigned addr)
{
    asm volatile("ldmatrix.sync.aligned.m8n8.x4.trans.shared.b16 {%0,%1,%2,%3}, [%4];\n"
                 : "=r"(r[0]), "=r"(r[1]), "=r"(r[2]), "=r"(r[3]) : "r"(addr));
}

__device__ __forceinline__ unsigned pack_h2(float a, float b)
{
    __half2 h = __floats2half2_rn(a, b);
    return *(unsigned*)&h;
}

__device__ __forceinline__ void cp_async16(unsigned saddr, const void* gaddr)
{
    asm volatile("cp.async.cg.shared.global [%0], [%1], 16;\n"
                 :: "r"(saddr), "l"(gaddr));
}

#define CP_COMMIT() asm volatile("cp.async.commit_group;\n" ::: "memory")
#define CP_WAIT1()  asm volatile("cp.async.wait_group 1;\n" ::: "memory")
#define CP_WAIT2()  asm volatile("cp.async.wait_group 2;\n" ::: "memory")

// ---------------------------------------------------------------------------
// Split-bf16 tensor-core GEMM (NT), 2-stage cp.async pipeline.
// C = A @ W^T + bias.  Tile 128x128, K-chunk 32, 256 threads = 8 warps.
// mode 0: fp32 C[m*1024+n];  mode 1: fp16 out, head-split layout.
// ---------------------------------------------------------------------------
#define GKC 32
#define GLD 40                       // smem row stride in bf16 (80B)
#define G_MTX_B (128 * GLD * 2)      // bytes per matrix per stage (10240)
#define G_STG_B (4 * G_MTX_B)        // bytes per stage (40960)
#define G_SMEM_TOTAL (2 * G_STG_B)   // 81920

__global__ __launch_bounds__(256) void gemm_bf16_split(
    const __nv_bfloat16* __restrict__ Ahi, const __nv_bfloat16* __restrict__ Alo,
    const __nv_bfloat16* __restrict__ Bhi, const __nv_bfloat16* __restrict__ Blo,
    const float* __restrict__ bias, float* __restrict__ C,
    __half* __restrict__ H16, int mode)
{
    extern __shared__ __align__(128) char smG[];
    const unsigned sbase = smem_u32(smG);

    const int tid = threadIdx.x;
    const int wid = tid >> 5;
    const int lane = tid & 31;
    const int wm = wid >> 2;
    const int wn = wid & 3;
    const int rowBase = blockIdx.y * 128;
    const int colBase = blockIdx.x * 128;

    const __nv_bfloat16* gsrc[4] = {
        Ahi + (size_t)rowBase * NU, Alo + (size_t)rowBase * NU,
        Bhi + (size_t)colBase * NU, Blo + (size_t)colBase * NU};

    unsigned aAddrH[4], aAddrL[4], bAddrH[4], bAddrL[4];
#pragma unroll
    for (int mt = 0; mt < 4; mt++) {
        const int r = wm * 64 + mt * 16 + (lane & 15);
        const int c = ((lane >> 4) & 1) * 8;
        aAddrH[mt] = sbase + 0 * G_MTX_B + (r * GLD + c) * 2;
        aAddrL[mt] = sbase + 1 * G_MTX_B + (r * GLD + c) * 2;
    }
#pragma unroll
    for (int nt = 0; nt < 4; nt++) {
        const int r = wn * 32 + nt * 8 + (lane & 7);
        const int c = ((lane >> 3) & 1) * 8;
        bAddrH[nt] = sbase + 2 * G_MTX_B + (r * GLD + c) * 2;
        bAddrL[nt] = sbase + 3 * G_MTX_B + (r * GLD + c) * 2;
    }

    float acc[4][4][4];
#pragma unroll
    for (int i = 0; i < 4; i++)
#pragma unroll
        for (int j = 0; j < 4; j++)
#pragma unroll
            for (int c = 0; c < 4; c++) acc[i][j][c] = 0.f;

    auto load_stage = [&](int st, int chunk) {
        const int k0 = chunk * GKC;
        const unsigned stb = sbase + st * G_STG_B;
#pragma unroll
        for (int i = 0; i < 8; i++) {
            const int lin = tid + i * 256;
            const int mtx = lin >> 9;
            const int rem = lin & 511;
            const int row = rem >> 2;
            const int ch = rem & 3;
            cp_async16(stb + mtx * G_MTX_B + (row * GLD + ch * 8) * 2,
                       gsrc[mtx] + (size_t)row * NU + k0 + ch * 8);
        }
    };

    const int NCHUNK = NU / GKC;  // 32
    load_stage(0, 0); CP_COMMIT();
    load_stage(1, 1); CP_COMMIT();

    for (int chunk = 0; chunk < NCHUNK; chunk++) {
        const int st = chunk & 1;
        const unsigned stoff = st * G_STG_B;
        CP_WAIT1();
        __syncthreads();

#pragma unroll
        for (int ks = 0; ks < 2; ks++) {
            const unsigned koff = stoff + ks * 32;  // 16 bf16 cols
            unsigned bh[4][2], bl[4][2];
#pragma unroll
            for (int nt = 0; nt < 4; nt++) {
                ldsm_x2(bh[nt], bAddrH[nt] + koff);
                ldsm_x2(bl[nt], bAddrL[nt] + koff);
            }
#pragma unroll
            for (int mt = 0; mt < 4; mt++) {
                unsigned ah[4], al[4];
                ldsm_x4(ah, aAddrH[mt] + koff);
                ldsm_x4(al, aAddrL[mt] + koff);
#pragma unroll
                for (int nt = 0; nt < 4; nt++) mma_bf16(acc[mt][nt], ah, bh[nt]);
#pragma unroll
                for (int nt = 0; nt < 4; nt++) mma_bf16(acc[mt][nt], ah, bl[nt]);
#pragma unroll
                for (int nt = 0; nt < 4; nt++) mma_bf16(acc[mt][nt], al, bh[nt]);
            }
        }

        __syncthreads();
        if (chunk + 2 < NCHUNK) load_stage(st, chunk + 2);
        CP_COMMIT();
    }

    // Epilogue
#pragma unroll
    for (int mt = 0; mt < 4; mt++) {
#pragma unroll
        for (int nt = 0; nt < 4; nt++) {
            const int m = rowBase + wm * 64 + mt * 16 + (lane >> 2);
            const int n = colBase + wn * 32 + nt * 8 + (lane & 3) * 2;
            const float b0 = bias[n];
            const float b1 = bias[n + 1];
            float v0x = acc[mt][nt][0] + b0, v0y = acc[mt][nt][1] + b1;
            float v1x = acc[mt][nt][2] + b0, v1y = acc[mt][nt][3] + b1;
            if (mode == 0) {
                *(float2*)&C[(size_t)m * NU + n] = make_float2(v0x, v0y);
                *(float2*)&C[(size_t)(m + 8) * NU + n] = make_float2(v1x, v1y);
            } else {
                const int h = n >> 6, d = n & 63;
#pragma unroll
                for (int rr = 0; rr < 2; rr++) {
                    const int mr = m + rr * 8;
                    const int b = mr >> 11, t = mr & 2047;
                    const size_t idx = (((size_t)(b * HH + h) * TT) + t) * DD + d;
                    float vx = rr ? v1x : v0x, vy = rr ? v1y : v0y;
                    __half2 hv = __floats2half2_rn(vx, vy);
                    *(__half2*)&H16[idx] = hv;
                }
            }
        }
    }
}

// ---------------------------------------------------------------------------
// fp16 tensor-core flash attention, 3-stage cp.async KV pipeline.
// Grid: (T/128, B*H). 256 threads = 8 warps; warp owns 16 query rows.
// Single-precision fp16 operands (error ~2^-12, within budget), fp32 accum.
// ---------------------------------------------------------------------------
#define ATQ 128
#define AKV 64
#define SVLD 72                       // row stride fp16 (144B)
#define A_MTX_B (AKV * SVLD * 2)      // 9216 bytes per matrix (K or V)
#define A_STG_B (2 * A_MTX_B)         // 18432 per stage
#define A_NSTG 3
#define A_SMEM_TOTAL (A_NSTG * A_STG_B)  // 55296

__global__ __launch_bounds__(256) void attn_fp16()
{
    extern __shared__ __align__(128) char smA[];
    const unsigned sbase = smem_u32(smA);
    __half* smh = (__half*)smA;

    const int tid = threadIdx.x;
    const int lane = tid & 31;
    const int wid = tid >> 5;
    const int bh = blockIdx.y;
    const int q0 = blockIdx.x * ATQ;

    const size_t kvbase = (size_t)bh * TT * DD;
    const __half* Qp = g_q16 + kvbase + (size_t)q0 * DD;
    const __half* Kp = g_k16 + kvbase;
    const __half* Vp = g_v16 + kvbase;

    // ---- Stage Q (128x64 fp16) into stage-0 smem, pull frags to regs ----
    {
        const int r = tid >> 1;
        const int c = (tid & 1) * 32;
        const uint4* gq = (const uint4*)(Qp + (size_t)r * DD + c);
        uint4* dq = (uint4*)(smh + r * SVLD + c);
#pragma unroll
        for (int i = 0; i < 4; i++) dq[i] = gq[i];
    }
    __syncthreads();

    unsigned qf[4][4];
    {
        const int qrow = wid * 16 + (lane & 15);
        const int ccol = ((lane >> 4) & 1) * 8;
#pragma unroll
        for (int kk = 0; kk < 4; kk++)
            ldsm_x4(qf[kk], smem_u32(smh + qrow * SVLD + kk * 16 + ccol));
    }
    __syncthreads();

    // ldmatrix base addresses (stage 0): K slot 0, V slot 1
    unsigned kAddr[4];
#pragma unroll
    for (int np = 0; np < 4; np++) {
        const int r = np * 16 + (lane & 15);
        const int c = ((lane >> 4) & 1) * 8;
        kAddr[np] = sbase + (r * SVLD + c) * 2;
    }
    unsigned vAddr[4];
#pragma unroll
    for (int dp = 0; dp < 4; dp++) {
        const int r = (lane & 15);
        const int c = dp * 16 + ((lane >> 4) & 1) * 8;
        vAddr[dp] = sbase + A_MTX_B + (r * SVLD + c) * 2;
    }

    // async KV tile loader: 2 matrices x 64 rows x 8 chunks = 1024 x16B
    auto load_tile = [&](int st, int jt) {
        const unsigned stb = sbase + st * A_STG_B;
        const size_t goff = (size_t)jt * AKV * DD;
#pragma unroll
        for (int i = 0; i < 4; i++) {
            const int lin = tid + i * 256;
            const int mtx = lin >> 9;
            const int rem = lin & 511;
            const int row = rem >> 3;
            const int ch = rem & 7;
            cp_async16(stb + mtx * A_MTX_B + (row * SVLD + ch * 8) * 2,
                       (mtx ? Vp : Kp) + goff + row * DD + ch * 8);
        }
    };

    float o[8][4];
#pragma unroll
    for (int j = 0; j < 8; j++)
#pragma unroll
        for (int c = 0; c < 4; c++) o[j][c] = 0.f;
    float m_lo = -1e30f, m_hi = -1e30f, l_lo = 0.f, l_hi = 0.f;

    const int NT = TT / AKV;  // 32
    load_tile(0, 0); CP_COMMIT();
    load_tile(1, 1); CP_COMMIT();
    load_tile(2, 2); CP_COMMIT();

    int st = 0;
    for (int jt = 0; jt < NT; jt++) {
        const unsigned stoff = st * A_STG_B;
        CP_WAIT2();
        __syncthreads();

        // ---- S = Q K^T (fp16) ----
        float s[8][4];
#pragma unroll
        for (int j = 0; j < 8; j++)
#pragma unroll
            for (int c = 0; c < 4; c++) s[j][c] = 0.f;

#pragma unroll
        for (int kk = 0; kk < 4; kk++) {
            const unsigned koff = stoff + kk * 32;
#pragma unroll
            for (int np = 0; np < 4; np++) {
                unsigned k4[4];
                ldsm_x4(k4, kAddr[np] + koff);
                unsigned bhe[2] = {k4[0], k4[2]}, bho[2] = {k4[1], k4[3]};
                mma_f16(s[2 * np], qf[kk], bhe);
                mma_f16(s[2 * np + 1], qf[kk], bho);
            }
        }

        // ---- Online softmax on fragments ----
        float tml = -1e30f, tmh = -1e30f;
#pragma unroll
        for (int j = 0; j < 8; j++) {
            tml = fmaxf(tml, fmaxf(s[j][0], s[j][1]));
            tmh = fmaxf(tmh, fmaxf(s[j][2], s[j][3]));
        }
        tml = fmaxf(tml, __shfl_xor_sync(0xffffffff, tml, 1));
        tml = fmaxf(tml, __shfl_xor_sync(0xffffffff, tml, 2));
        tmh = fmaxf(tmh, __shfl_xor_sync(0xffffffff, tmh, 1));
        tmh = fmaxf(tmh, __shfl_xor_sync(0xffffffff, tmh, 2));

        const float mnl = fmaxf(m_lo, tml);
        const float mnh = fmaxf(m_hi, tmh);
        const float al = __expf((m_lo - mnl) * 0.125f);
        const float ah = __expf((m_hi - mnh) * 0.125f);
        m_lo = mnl; m_hi = mnh;
        const float cl = mnl * 0.125f, ch = mnh * 0.125f;

        float suml = 0.f, sumh = 0.f;
#pragma unroll
        for (int j = 0; j < 8; j++) {
            float p0 = __expf(fmaf(s[j][0], 0.125f, -cl));
            float p1 = __expf(fmaf(s[j][1], 0.125f, -cl));
            float p2 = __expf(fmaf(s[j][2], 0.125f, -ch));
            float p3 = __expf(fmaf(s[j][3], 0.125f, -ch));
            s[j][0] = p0; s[j][1] = p1; s[j][2] = p2; s[j][3] = p3;
            suml += p0 + p1; sumh += p2 + p3;
        }
        suml += __shfl_xor_sync(0xffffffff, suml, 1);
        suml += __shfl_xor_sync(0xffffffff, suml, 2);
        sumh += __shfl_xor_sync(0xffffffff, sumh, 1);
        sumh += __shfl_xor_sync(0xffffffff, sumh, 2);
        l_lo = l_lo * al + suml;
        l_hi = l_hi * ah + sumh;

#pragma unroll
        for (int j = 0; j < 8; j++) {
            o[j][0] *= al; o[j][1] *= al; o[j][2] *= ah; o[j][3] *= ah;
        }

        // ---- O += P V (fp16 P in registers) ----
#pragma unroll
        for (int kk = 0; kk < 4; kk++) {
            unsigned pf[4];
            pf[0] = pack_h2(s[2 * kk][0], s[2 * kk][1]);
            pf[1] = pack_h2(s[2 * kk][2], s[2 * kk][3]);
            pf[2] = pack_h2(s[2 * kk + 1][0], s[2 * kk + 1][1]);
            pf[3] = pack_h2(s[2 * kk + 1][2], s[2 * kk + 1][3]);

            const unsigned roff = stoff + kk * 16 * SVLD * 2;
#pragma unroll
            for (int dp = 0; dp < 4; dp++) {
                unsigned v4[4];
                ldsm_x4t(v4, vAddr[dp] + roff);
                unsigned bhe[2] = {v4[0], v4[1]}, bho[2] = {v4[2], v4[3]};
                mma_f16(o[2 * dp], pf, bhe);
                mma_f16(o[2 * dp + 1], pf, bho);
            }
        }

        __syncthreads();
        if (jt + A_NSTG < NT) load_tile(st, jt + A_NSTG);
        CP_COMMIT();
        st = (st + 1 == A_NSTG) ? 0 : st + 1;
    }

    // ---- Epilogue: normalize, split to bf16, write (b,t,h,d) ----
    const int b = bh >> 4;
    const int h = bh & 15;
    const float invl = 1.f / l_lo;
    const float invh = 1.f / l_hi;
    const int t_lo = q0 + wid * 16 + (lane >> 2);
    const int t_hi = t_lo + 8;

#pragma unroll
    for (int j = 0; j < 8; j++) {
        const int d = j * 8 + (lane & 3) * 2;
        {
            const size_t idx = ((size_t)(b * TT + t_lo) * HH + h) * DD + d;
            float vx = o[j][0] * invl, vy = o[j][1] * invl;
            __nv_bfloat162 hh = __float22bfloat162_rn(make_float2(vx, vy));
            float2 hf = __bfloat1622float2(hh);
            __nv_bfloat162 ll = __float22bfloat162_rn(make_float2(vx - hf.x, vy - hf.y));
            *(__nv_bfloat162*)&g_chi[idx] = hh;
            *(__nv_bfloat162*)&g_clo[idx] = ll;
        }
        {
            const size_t idx = ((size_t)(b * TT + t_hi) * HH + h) * DD + d;
            float vx = o[j][2] * invh, vy = o[j][3] * invh;
            __nv_bfloat162 hh = __float22bfloat162_rn(make_float2(vx, vy));
            float2 hf = __bfloat1622float2(hh);
            __nv_bfloat162 ll = __float22bfloat162_rn(make_float2(vx - hf.x, vy - hf.y));
            *(__nv_bfloat162*)&g_chi[idx] = hh;
            *(__nv_bfloat162*)&g_clo[idx] = ll;
        }
    }
}

// ---------------------------------------------------------------------------
// Launch
// ---------------------------------------------------------------------------
extern "C" void kernel_launch(void* const* d_in, const int* in_sizes, int n_in,
                              void* d_out, int out_size)
{
    const float* x  = (const float*)d_in[0];
    const float* Wq = (const float*)d_in[1];
    const float* bq = (const float*)d_in[2];
    const float* Wk = (const float*)d_in[3];
    const float* bk = (const float*)d_in[4];
    const float* Wv = (const float*)d_in[5];
    const float* bv = (const float*)d_in[6];
    const float* Wo = (const float*)d_in[7];
    const float* bo = (const float*)d_in[8];
    float* out = (float*)d_out;

    __nv_bfloat16 *xhi, *xlo, *whi, *wlo, *chi, *clo;
    __half *q16, *k16, *v16;
    cudaGetSymbolAddress((void**)&xhi, g_xhi);
    cudaGetSymbolAddress((void**)&xlo, g_xlo);
    cudaGetSymbolAddress((void**)&whi, g_whi);
    cudaGetSymbolAddress((void**)&wlo, g_wlo);
    cudaGetSymbolAddress((void**)&chi, g_chi);
    cudaGetSymbolAddress((void**)&clo, g_clo);
    cudaGetSymbolAddress((void**)&q16, g_q16);
    cudaGetSymbolAddress((void**)&k16, g_k16);
    cudaGetSymbolAddress((void**)&v16, g_v16);

    const int n4x = (int)((size_t)MM * NU / 4);
    split_convert<<<(n4x + 255) / 256, 256>>>((const float4*)x, (uint2*)xhi,
                                              (uint2*)xlo, n4x);
    const int n4w = NU * NU / 4;
    const float* Ws[4] = {Wq, Wk, Wv, Wo};
    for (int w = 0; w < 4; w++) {
        split_convert<<<(n4w + 255) / 256, 256>>>(
            (const float4*)Ws[w],
            (uint2*)(whi + (size_t)w * NU * NU),
            (uint2*)(wlo + (size_t)w * NU * NU), n4w);
    }

    cudaFuncSetAttribute(gemm_bf16_split,
                         cudaFuncAttributeMaxDynamicSharedMemorySize,
                         G_SMEM_TOTAL);
    cudaFuncSetAttribute(attn_fp16,
                         cudaFuncAttributeMaxDynamicSharedMemorySize,
                         A_SMEM_TOTAL);

    const dim3 gGemm(NU / 128, MM / 128);  // (8, 64)

    gemm_bf16_split<<<gGemm, 256, G_SMEM_TOTAL>>>(
        xhi, xlo, whi, wlo, bq, nullptr, q16, 1);
    gemm_bf16_split<<<gGemm, 256, G_SMEM_TOTAL>>>(
        xhi, xlo, whi + (size_t)NU * NU, wlo + (size_t)NU * NU, bk, nullptr,
        k16, 1);
    gemm_bf16_split<<<gGemm, 256, G_SMEM_TOTAL>>>(
        xhi, xlo, whi + 2 * (size_t)NU * NU, wlo + 2 * (size_t)NU * NU, bv,
        nullptr, v16, 1);

    attn_fp16<<<dim3(TT / ATQ, BB * HH), 256, A_SMEM_TOTAL>>>();

    gemm_bf16_split<<<gGemm, 256, G_SMEM_TOTAL>>>(
        chi, clo, whi + 3 * (size_t)NU * NU, wlo + 3 * (size_t)NU * NU, bo, out,
        nullptr, 0);
}

// round 12
// speedup vs baseline: 7.7910x; 1.7338x over previous
#include <cuda_runtime.h>
#include <cuda_fp16.h>
#include <math.h>

// Problem constants
#define BB 4
#define TT 2048
#define HH 16
#define DD 64
#define NU 1024
#define MM (BB * TT)  // 8192

// Scratch (device globals: allocation-free)
__device__ __half g_x16[(size_t)MM * NU];
__device__ __half g_w16[4 * (size_t)NU * NU];
__device__ __half g_q16[(size_t)MM * NU];
__device__ __half g_k16[(size_t)MM * NU];
__device__ __half g_v16[(size_t)MM * NU];
__device__ __half g_c16[(size_t)MM * NU];

// ---------------------------------------------------------------------------
// fp32 -> fp16 conversion
// ---------------------------------------------------------------------------
__global__ __launch_bounds__(256) void to_half(
    const float4* __restrict__ in, uint2* __restrict__ out, int n4)
{
    int i = blockIdx.x * blockDim.x + threadIdx.x;
    if (i >= n4) return;
    float4 v = in[i];
    __half2 a = __floats2half2_rn(v.x, v.y);
    __half2 b = __floats2half2_rn(v.z, v.w);
    uint2 u;
    u.x = *(unsigned*)&a;
    u.y = *(unsigned*)&b;
    out[i] = u;
}

// ---------------------------------------------------------------------------
// Helpers
// ---------------------------------------------------------------------------
__device__ __forceinline__ unsigned smem_u32(const void* p)
{
    return (unsigned)__cvta_generic_to_shared(p);
}

__device__ __forceinline__ void mma_f16(float* d, const unsigned* a, const unsigned* b)
{
    asm volatile(
        "mma.sync.aligned.m16n8k16.row.col.f32.f16.f16.f32 "
        "{%0,%1,%2,%3}, {%4,%5,%6,%7}, {%8,%9}, {%0,%1,%2,%3};\n"
        : "+f"(d[0]), "+f"(d[1]), "+f"(d[2]), "+f"(d[3])
        : "r"(a[0]), "r"(a[1]), "r"(a[2]), "r"(a[3]), "r"(b[0]), "r"(b[1]));
}

__device__ __forceinline__ void ldsm_x4(unsigned* r, unsigned addr)
{
    asm volatile("ldmatrix.sync.aligned.m8n8.x4.shared.b16 {%0,%1,%2,%3}, [%4];\n"
                 : "=r"(r[0]), "=r"(r[1]), "=r"(r[2]), "=r"(r[3]) : "r"(addr));
}

__device__ __forceinline__ void ldsm_x2(unsigned* r, unsigned addr)
{
    asm volatile("ldmatrix.sync.aligned.m8n8.x2.shared.b16 {%0,%1}, [%2];\n"
                 : "=r"(r[0]), "=r"(r[1]) : "r"(addr));
}

__device__ __forceinline__ void ldsm_x4t(unsigned* r, unsigned addr)
{
    asm volatile("ldmatrix.sync.aligned.m8n8.x4.trans.shared.b16 {%0,%1,%2,%3}, [%4];\n"
                 : "=r"(r[0]), "=r"(r[1]), "=r"(r[2]), "=r"(r[3]) : "r"(addr));
}

__device__ __forceinline__ unsigned pack_h2(float a, float b)
{
    __half2 h = __floats2half2_rn(a, b);
    return *(unsigned*)&h;
}

__device__ __forceinline__ void cp_async16(unsigned saddr, const void* gaddr)
{
    asm volatile("cp.async.cg.shared.global [%0], [%1], 16;\n"
                 :: "r"(saddr), "l"(gaddr));
}

#define CP_COMMIT() asm volatile("cp.async.commit_group;\n" ::: "memory")
#define CP_WAIT2()  asm volatile("cp.async.wait_group 2;\n" ::: "memory")

// ---------------------------------------------------------------------------
// fp16 tensor-core GEMM (NT), 3-stage cp.async pipeline.
// C = A @ W^T + bias.  Tile 128x128, K-chunk 32, 256 threads = 8 warps.
// mode 1 (QKV fused): blockIdx.z selects weight/bias/output; fp16 out,
//                     head-split layout ((b*16+h)*2048+t)*64+d.
// mode 0 (O-proj):    fp32 out C[m*1024+n], grid.z == 1.
// ---------------------------------------------------------------------------
#define GKC 32
#define GLD 40                       // smem row stride in fp16 (80B)
#define G_MTX_B (128 * GLD * 2)      // 10240 bytes per matrix per stage
#define G_STG_B (2 * G_MTX_B)        // 20480 per stage
#define G_NSTG 3
#define G_SMEM_TOTAL (G_NSTG * G_STG_B)  // 61440

__global__ __launch_bounds__(256) void gemm_f16(
    const __half* __restrict__ A, const __half* __restrict__ Wb,
    const float* __restrict__ biasQ, const float* __restrict__ biasK,
    const float* __restrict__ biasV,
    __half* __restrict__ outQ, __half* __restrict__ outK,
    __half* __restrict__ outV, float* __restrict__ C, int mode)
{
    extern __shared__ __align__(128) char smG[];
    const unsigned sbase = smem_u32(smG);

    const int z = blockIdx.z;
    const __half* W = Wb + (size_t)z * NU * NU;
    const float* bias = (z == 0) ? biasQ : (z == 1) ? biasK : biasV;
    __half* H16 = (z == 0) ? outQ : (z == 1) ? outK : outV;

    const int tid = threadIdx.x;
    const int wid = tid >> 5;
    const int lane = tid & 31;
    const int wm = wid >> 2;
    const int wn = wid & 3;
    const int rowBase = blockIdx.y * 128;
    const int colBase = blockIdx.x * 128;

    const __half* Ap = A + (size_t)rowBase * NU;
    const __half* Wp = W + (size_t)colBase * NU;

    unsigned aAddr[4], bAddr[4];
#pragma unroll
    for (int mt = 0; mt < 4; mt++) {
        const int r = wm * 64 + mt * 16 + (lane & 15);
        const int c = ((lane >> 4) & 1) * 8;
        aAddr[mt] = sbase + (r * GLD + c) * 2;
    }
#pragma unroll
    for (int nt = 0; nt < 4; nt++) {
        const int r = wn * 32 + nt * 8 + (lane & 7);
        const int c = ((lane >> 3) & 1) * 8;
        bAddr[nt] = sbase + G_MTX_B + (r * GLD + c) * 2;
    }

    float acc[4][4][4];
#pragma unroll
    for (int i = 0; i < 4; i++)
#pragma unroll
        for (int j = 0; j < 4; j++)
#pragma unroll
            for (int c = 0; c < 4; c++) acc[i][j][c] = 0.f;

    // Loader: 2 matrices x 128 rows x 4 x16B chunks = 1024 ops, 4/thread
    auto load_stage = [&](int st, int chunk) {
        const int k0 = chunk * GKC;
        const unsigned stb = sbase + st * G_STG_B;
#pragma unroll
        for (int i = 0; i < 4; i++) {
            const int lin = tid + i * 256;
            const int mtx = lin >> 9;
            const int rem = lin & 511;
            const int row = rem >> 2;
            const int ch = rem & 3;
            cp_async16(stb + mtx * G_MTX_B + (row * GLD + ch * 8) * 2,
                       (mtx ? Wp : Ap) + (size_t)row * NU + k0 + ch * 8);
        }
    };

    const int NCHUNK = NU / GKC;  // 32
    load_stage(0, 0); CP_COMMIT();
    load_stage(1, 1); CP_COMMIT();
    load_stage(2, 2); CP_COMMIT();

    int st = 0;
    for (int chunk = 0; chunk < NCHUNK; chunk++) {
        const unsigned stoff = st * G_STG_B;
        CP_WAIT2();
        __syncthreads();

#pragma unroll
        for (int ks = 0; ks < 2; ks++) {
            const unsigned koff = stoff + ks * 32;  // 16 fp16 cols
            unsigned bfr[4][2];
#pragma unroll
            for (int nt = 0; nt < 4; nt++) ldsm_x2(bfr[nt], bAddr[nt] + koff);
#pragma unroll
            for (int mt = 0; mt < 4; mt++) {
                unsigned afr[4];
                ldsm_x4(afr, aAddr[mt] + koff);
#pragma unroll
                for (int nt = 0; nt < 4; nt++) mma_f16(acc[mt][nt], afr, bfr[nt]);
            }
        }

        __syncthreads();
        if (chunk + G_NSTG < NCHUNK) load_stage(st, chunk + G_NSTG);
        CP_COMMIT();
        st = (st + 1 == G_NSTG) ? 0 : st + 1;
    }

    // Epilogue
#pragma unroll
    for (int mt = 0; mt < 4; mt++) {
#pragma unroll
        for (int nt = 0; nt < 4; nt++) {
            const int m = rowBase + wm * 64 + mt * 16 + (lane >> 2);
            const int n = colBase + wn * 32 + nt * 8 + (lane & 3) * 2;
            const float b0 = bias[n];
            const float b1 = bias[n + 1];
            float v0x = acc[mt][nt][0] + b0, v0y = acc[mt][nt][1] + b1;
            float v1x = acc[mt][nt][2] + b0, v1y = acc[mt][nt][3] + b1;
            if (mode == 0) {
                *(float2*)&C[(size_t)m * NU + n] = make_float2(v0x, v0y);
                *(float2*)&C[(size_t)(m + 8) * NU + n] = make_float2(v1x, v1y);
            } else {
                const int h = n >> 6, d = n & 63;
#pragma unroll
                for (int rr = 0; rr < 2; rr++) {
                    const int mr = m + rr * 8;
                    const int b = mr >> 11, t = mr & 2047;
                    const size_t idx = (((size_t)(b * HH + h) * TT) + t) * DD + d;
                    float vx = rr ? v1x : v0x, vy = rr ? v1y : v0y;
                    __half2 hv = __floats2half2_rn(vx, vy);
                    *(__half2*)&H16[idx] = hv;
                }
            }
        }
    }
}

// ---------------------------------------------------------------------------
// fp16 tensor-core flash attention, 3-stage cp.async KV pipeline.
// Grid: (T/128, B*H). 256 threads = 8 warps; warp owns 16 query rows.
// ---------------------------------------------------------------------------
#define ATQ 128
#define AKV 64
#define SVLD 72                       // row stride fp16 (144B)
#define A_MTX_B (AKV * SVLD * 2)      // 9216 bytes per matrix (K or V)
#define A_STG_B (2 * A_MTX_B)         // 18432 per stage
#define A_NSTG 3
#define A_SMEM_TOTAL (A_NSTG * A_STG_B)  // 55296

__global__ __launch_bounds__(256) void attn_fp16()
{
    extern __shared__ __align__(128) char smA[];
    const unsigned sbase = smem_u32(smA);
    __half* smh = (__half*)smA;

    const int tid = threadIdx.x;
    const int lane = tid & 31;
    const int wid = tid >> 5;
    const int bh = blockIdx.y;
    const int q0 = blockIdx.x * ATQ;

    const size_t kvbase = (size_t)bh * TT * DD;
    const __half* Qp = g_q16 + kvbase + (size_t)q0 * DD;
    const __half* Kp = g_k16 + kvbase;
    const __half* Vp = g_v16 + kvbase;

    // ---- Stage Q (128x64 fp16) into stage-0 smem, pull frags to regs ----
    {
        const int r = tid >> 1;
        const int c = (tid & 1) * 32;
        const uint4* gq = (const uint4*)(Qp + (size_t)r * DD + c);
        uint4* dq = (uint4*)(smh + r * SVLD + c);
#pragma unroll
        for (int i = 0; i < 4; i++) dq[i] = gq[i];
    }
    __syncthreads();

    unsigned qf[4][4];
    {
        const int qrow = wid * 16 + (lane & 15);
        const int ccol = ((lane >> 4) & 1) * 8;
#pragma unroll
        for (int kk = 0; kk < 4; kk++)
            ldsm_x4(qf[kk], smem_u32(smh + qrow * SVLD + kk * 16 + ccol));
    }
    __syncthreads();

    unsigned kAddr[4];
#pragma unroll
    for (int np = 0; np < 4; np++) {
        const int r = np * 16 + (lane & 15);
        const int c = ((lane >> 4) & 1) * 8;
        kAddr[np] = sbase + (r * SVLD + c) * 2;
    }
    unsigned vAddr[4];
#pragma unroll
    for (int dp = 0; dp < 4; dp++) {
        const int r = (lane & 15);
        const int c = dp * 16 + ((lane >> 4) & 1) * 8;
        vAddr[dp] = sbase + A_MTX_B + (r * SVLD + c) * 2;
    }

    auto load_tile = [&](int st, int jt) {
        const unsigned stb = sbase + st * A_STG_B;
        const size_t goff = (size_t)jt * AKV * DD;
#pragma unroll
        for (int i = 0; i < 4; i++) {
            const int lin = tid + i * 256;
            const int mtx = lin >> 9;
            const int rem = lin & 511;
            const int row = rem >> 3;
            const int ch = rem & 7;
            cp_async16(stb + mtx * A_MTX_B + (row * SVLD + ch * 8) * 2,
                       (mtx ? Vp : Kp) + goff + row * DD + ch * 8);
        }
    };

    float o[8][4];
#pragma unroll
    for (int j = 0; j < 8; j++)
#pragma unroll
        for (int c = 0; c < 4; c++) o[j][c] = 0.f;
    float m_lo = -1e30f, m_hi = -1e30f, l_lo = 0.f, l_hi = 0.f;

    const int NT = TT / AKV;  // 32
    load_tile(0, 0); CP_COMMIT();
    load_tile(1, 1); CP_COMMIT();
    load_tile(2, 2); CP_COMMIT();

    int st = 0;
    for (int jt = 0; jt < NT; jt++) {
        const unsigned stoff = st * A_STG_B;
        CP_WAIT2();
        __syncthreads();

        // ---- S = Q K^T ----
        float s[8][4];
#pragma unroll
        for (int j = 0; j < 8; j++)
#pragma unroll
            for (int c = 0; c < 4; c++) s[j][c] = 0.f;

#pragma unroll
        for (int kk = 0; kk < 4; kk++) {
            const unsigned koff = stoff + kk * 32;
#pragma unroll
            for (int np = 0; np < 4; np++) {
                unsigned k4[4];
                ldsm_x4(k4, kAddr[np] + koff);
                unsigned bhe[2] = {k4[0], k4[2]}, bho[2] = {k4[1], k4[3]};
                mma_f16(s[2 * np], qf[kk], bhe);
                mma_f16(s[2 * np + 1], qf[kk], bho);
            }
        }

        // ---- Online softmax on fragments ----
        float tml = -1e30f, tmh = -1e30f;
#pragma unroll
        for (int j = 0; j < 8; j++) {
            tml = fmaxf(tml, fmaxf(s[j][0], s[j][1]));
            tmh = fmaxf(tmh, fmaxf(s[j][2], s[j][3]));
        }
        tml = fmaxf(tml, __shfl_xor_sync(0xffffffff, tml, 1));
        tml = fmaxf(tml, __shfl_xor_sync(0xffffffff, tml, 2));
        tmh = fmaxf(tmh, __shfl_xor_sync(0xffffffff, tmh, 1));
        tmh = fmaxf(tmh, __shfl_xor_sync(0xffffffff, tmh, 2));

        const float mnl = fmaxf(m_lo, tml);
        const float mnh = fmaxf(m_hi, tmh);
        const float al = __expf((m_lo - mnl) * 0.125f);
        const float ah = __expf((m_hi - mnh) * 0.125f);
        m_lo = mnl; m_hi = mnh;
        const float cl = mnl * 0.125f, ch = mnh * 0.125f;

        float suml = 0.f, sumh = 0.f;
#pragma unroll
        for (int j = 0; j < 8; j++) {
            float p0 = __expf(fmaf(s[j][0], 0.125f, -cl));
            float p1 = __expf(fmaf(s[j][1], 0.125f, -cl));
            float p2 = __expf(fmaf(s[j][2], 0.125f, -ch));
            float p3 = __expf(fmaf(s[j][3], 0.125f, -ch));
            s[j][0] = p0; s[j][1] = p1; s[j][2] = p2; s[j][3] = p3;
            suml += p0 + p1; sumh += p2 + p3;
        }
        suml += __shfl_xor_sync(0xffffffff, suml, 1);
        suml += __shfl_xor_sync(0xffffffff, suml, 2);
        sumh += __shfl_xor_sync(0xffffffff, sumh, 1);
        sumh += __shfl_xor_sync(0xffffffff, sumh, 2);
        l_lo = l_lo * al + suml;
        l_hi = l_hi * ah + sumh;

#pragma unroll
        for (int j = 0; j < 8; j++) {
            o[j][0] *= al; o[j][1] *= al; o[j][2] *= ah; o[j][3] *= ah;
        }

        // ---- O += P V ----
#pragma unroll
        for (int kk = 0; kk < 4; kk++) {
            unsigned pf[4];
            pf[0] = pack_h2(s[2 * kk][0], s[2 * kk][1]);
            pf[1] = pack_h2(s[2 * kk][2], s[2 * kk][3]);
            pf[2] = pack_h2(s[2 * kk + 1][0], s[2 * kk + 1][1]);
            pf[3] = pack_h2(s[2 * kk + 1][2], s[2 * kk + 1][3]);

            const unsigned roff = stoff + kk * 16 * SVLD * 2;
#pragma unroll
            for (int dp = 0; dp < 4; dp++) {
                unsigned v4[4];
                ldsm_x4t(v4, vAddr[dp] + roff);
                unsigned bhe[2] = {v4[0], v4[1]}, bho[2] = {v4[2], v4[3]};
                mma_f16(o[2 * dp], pf, bhe);
                mma_f16(o[2 * dp + 1], pf, bho);
            }
        }

        __syncthreads();
        if (jt + A_NSTG < NT) load_tile(st, jt + A_NSTG);
        CP_COMMIT();
        st = (st + 1 == A_NSTG) ? 0 : st + 1;
    }

    // ---- Epilogue: normalize, write fp16 ctx (b,t,h,d) ----
    const int b = bh >> 4;
    const int h = bh & 15;
    const float invl = 1.f / l_lo;
    const float invh = 1.f / l_hi;
    const int t_lo = q0 + wid * 16 + (lane >> 2);
    const int t_hi = t_lo + 8;

#pragma unroll
    for (int j = 0; j < 8; j++) {
        const int d = j * 8 + (lane & 3) * 2;
        {
            const size_t idx = ((size_t)(b * TT + t_lo) * HH + h) * DD + d;
            __half2 hv = __floats2half2_rn(o[j][0] * invl, o[j][1] * invl);
            *(__half2*)&g_c16[idx] = hv;
        }
        {
            const size_t idx = ((size_t)(b * TT + t_hi) * HH + h) * DD + d;
            __half2 hv = __floats2half2_rn(o[j][2] * invh, o[j][3] * invh);
            *(__half2*)&g_c16[idx] = hv;
        }
    }
}

// ---------------------------------------------------------------------------
// Launch
// ---------------------------------------------------------------------------
extern "C" void kernel_launch(void* const* d_in, const int* in_sizes, int n_in,
                              void* d_out, int out_size)
{
    const float* x  = (const float*)d_in[0];
    const float* Wq = (const float*)d_in[1];
    const float* bq = (const float*)d_in[2];
    const float* Wk = (const float*)d_in[3];
    const float* bk = (const float*)d_in[4];
    const float* Wv = (const float*)d_in[5];
    const float* bv = (const float*)d_in[6];
    const float* Wo = (const float*)d_in[7];
    const float* bo = (const float*)d_in[8];
    float* out = (float*)d_out;

    __half *x16, *w16, *q16, *k16, *v16, *c16;
    cudaGetSymbolAddress((void**)&x16, g_x16);
    cudaGetSymbolAddress((void**)&w16, g_w16);
    cudaGetSymbolAddress((void**)&q16, g_q16);
    cudaGetSymbolAddress((void**)&k16, g_k16);
    cudaGetSymbolAddress((void**)&v16, g_v16);
    cudaGetSymbolAddress((void**)&c16, g_c16);

    const int n4x = (int)((size_t)MM * NU / 4);
    to_half<<<(n4x + 255) / 256, 256>>>((const float4*)x, (uint2*)x16, n4x);
    const int n4w = NU * NU / 4;
    const float* Ws[4] = {Wq, Wk, Wv, Wo};
    for (int w = 0; w < 4; w++) {
        to_half<<<(n4w + 255) / 256, 256>>>(
            (const float4*)Ws[w], (uint2*)(w16 + (size_t)w * NU * NU), n4w);
    }

    cudaFuncSetAttribute(gemm_f16,
                         cudaFuncAttributeMaxDynamicSharedMemorySize,
                         G_SMEM_TOTAL);
    cudaFuncSetAttribute(attn_fp16,
                         cudaFuncAttributeMaxDynamicSharedMemorySize,
                         A_SMEM_TOTAL);

    // Fused Q/K/V projections (grid.z selects weight/bias/output)
    gemm_f16<<<dim3(NU / 128, MM / 128, 3), 256, G_SMEM_TOTAL>>>(
        x16, w16, bq, bk, bv, q16, k16, v16, nullptr, 1);

    attn_fp16<<<dim3(TT / ATQ, BB * HH), 256, A_SMEM_TOTAL>>>();

    // O-projection
    gemm_f16<<<dim3(NU / 128, MM / 128, 1), 256, G_SMEM_TOTAL>>>(
        c16, w16 + 3 * (size_t)NU * NU, bo, nullptr, nullptr,
        nullptr, nullptr, nullptr, out, 0);
}

// round 13
// speedup vs baseline: 8.1591x; 1.0472x over previous
#include <cuda_runtime.h>
#include <cuda_fp16.h>
#include <math.h>

// Problem constants
#define BB 4
#define TT 2048
#define HH 16
#define DD 64
#define NU 1024
#define MM (BB * TT)  // 8192

// Scratch (device globals: allocation-free)
__device__ __half g_x16[(size_t)MM * NU];
__device__ __half g_w16[4 * (size_t)NU * NU];
__device__ __half g_q16[(size_t)MM * NU];
__device__ __half g_k16[(size_t)MM * NU];
__device__ __half g_v16[(size_t)MM * NU];
__device__ __half g_c16[(size_t)MM * NU];

// ---------------------------------------------------------------------------
// Fused fp32 -> fp16 conversion: x (MM*NU) followed by 4 weights (NU*NU each)
// Grid-stride over float4 groups.
// ---------------------------------------------------------------------------
#define N4X ((size_t)MM * NU / 4)      // 2097152
#define N4W ((size_t)NU * NU / 4)      // 262144
#define N4TOT (N4X + 4 * N4W)          // 3145728

__global__ __launch_bounds__(256) void to_half_all(
    const float4* __restrict__ x,
    const float4* __restrict__ wq, const float4* __restrict__ wk,
    const float4* __restrict__ wv, const float4* __restrict__ wo,
    uint2* __restrict__ x16, uint2* __restrict__ w16)
{
    const int stride = gridDim.x * blockDim.x;
    for (size_t i = blockIdx.x * blockDim.x + threadIdx.x; i < N4TOT;
         i += stride) {
        const float4* src;
        uint2* dst;
        if (i < N4X) {
            src = x + i;
            dst = x16 + i;
        } else {
            const size_t j = i - N4X;
            const size_t w = j >> 18;          // / N4W
            const size_t r = j & (N4W - 1);
            src = (w == 0 ? wq : w == 1 ? wk : w == 2 ? wv : wo) + r;
            dst = w16 + w * N4W + r;
        }
        float4 v = *src;
        __half2 a = __floats2half2_rn(v.x, v.y);
        __half2 b = __floats2half2_rn(v.z, v.w);
        uint2 u;
        u.x = *(unsigned*)&a;
        u.y = *(unsigned*)&b;
        *dst = u;
    }
}

// ---------------------------------------------------------------------------
// Helpers
// ---------------------------------------------------------------------------
__device__ __forceinline__ unsigned smem_u32(const void* p)
{
    return (unsigned)__cvta_generic_to_shared(p);
}

__device__ __forceinline__ void mma_f16(float* d, const unsigned* a, const unsigned* b)
{
    asm volatile(
        "mma.sync.aligned.m16n8k16.row.col.f32.f16.f16.f32 "
        "{%0,%1,%2,%3}, {%4,%5,%6,%7}, {%8,%9}, {%0,%1,%2,%3};\n"
        : "+f"(d[0]), "+f"(d[1]), "+f"(d[2]), "+f"(d[3])
        : "r"(a[0]), "r"(a[1]), "r"(a[2]), "r"(a[3]), "r"(b[0]), "r"(b[1]));
}

__device__ __forceinline__ void ldsm_x4(unsigned* r, unsigned addr)
{
    asm volatile("ldmatrix.sync.aligned.m8n8.x4.shared.b16 {%0,%1,%2,%3}, [%4];\n"
                 : "=r"(r[0]), "=r"(r[1]), "=r"(r[2]), "=r"(r[3]) : "r"(addr));
}

__device__ __forceinline__ void ldsm_x4t(unsigned* r, unsigned addr)
{
    asm volatile("ldmatrix.sync.aligned.m8n8.x4.trans.shared.b16 {%0,%1,%2,%3}, [%4];\n"
                 : "=r"(r[0]), "=r"(r[1]), "=r"(r[2]), "=r"(r[3]) : "r"(addr));
}

__device__ __forceinline__ unsigned pack_h2(float a, float b)
{
    __half2 h = __floats2half2_rn(a, b);
    return *(unsigned*)&h;
}

__device__ __forceinline__ void cp_async16(unsigned saddr, const void* gaddr)
{
    asm volatile("cp.async.cg.shared.global [%0], [%1], 16;\n"
                 :: "r"(saddr), "l"(gaddr));
}

#define CP_COMMIT() asm volatile("cp.async.commit_group;\n" ::: "memory")
#define CP_WAIT1()  asm volatile("cp.async.wait_group 1;\n" ::: "memory")
#define CP_WAIT2()  asm volatile("cp.async.wait_group 2;\n" ::: "memory")

// ---------------------------------------------------------------------------
// fp16 tensor-core GEMM (NT), 2-stage cp.async pipeline, K-chunk 64.
// C = A @ W^T + bias.  Tile 128x128, 256 threads = 8 warps (2m x 4n).
// mode 1 (QKV fused): blockIdx.z selects weight/bias/output; fp16 out,
//                     head-split layout ((b*16+h)*2048+t)*64+d.
// mode 0 (O-proj):    fp32 out C[m*1024+n], grid.z == 1.
// ---------------------------------------------------------------------------
#define GKC 64
#define GLD 72                       // smem row stride in fp16 (144B)
#define G_MTX_B (128 * GLD * 2)      // 18432 bytes per matrix per stage
#define G_STG_B (2 * G_MTX_B)        // 36864 per stage
#define G_SMEM_TOTAL (2 * G_STG_B)   // 73728

__global__ __launch_bounds__(256) void gemm_f16(
    const __half* __restrict__ A, const __half* __restrict__ Wb,
    const float* __restrict__ biasQ, const float* __restrict__ biasK,
    const float* __restrict__ biasV,
    __half* __restrict__ outQ, __half* __restrict__ outK,
    __half* __restrict__ outV, float* __restrict__ C, int mode)
{
    extern __shared__ __align__(128) char smG[];
    const unsigned sbase = smem_u32(smG);

    const int z = blockIdx.z;
    const __half* W = Wb + (size_t)z * NU * NU;
    const float* bias = (z == 0) ? biasQ : (z == 1) ? biasK : biasV;
    __half* H16 = (z == 0) ? outQ : (z == 1) ? outK : outV;

    const int tid = threadIdx.x;
    const int wid = tid >> 5;
    const int lane = tid & 31;
    const int wm = wid >> 2;
    const int wn = wid & 3;
    const int rowBase = blockIdx.y * 128;
    const int colBase = blockIdx.x * 128;

    const __half* Ap = A + (size_t)rowBase * NU;
    const __half* Wp = W + (size_t)colBase * NU;

    // A fragments: per mt, ldsm_x4 (16 rows x 16 cols)
    unsigned aAddr[4];
#pragma unroll
    for (int mt = 0; mt < 4; mt++) {
        const int r = wm * 64 + mt * 16 + (lane & 15);
        const int c = ((lane >> 4) & 1) * 8;
        aAddr[mt] = sbase + (r * GLD + c) * 2;
    }
    // B fragments: per np (pair of 8-col n-tiles), ldsm_x4:
    //   lanes0-7 rows0-7 k0 | lanes8-15 rows8-15 k0 |
    //   lanes16-23 rows0-7 k8 | lanes24-31 rows8-15 k8
    unsigned bAddr[2];
#pragma unroll
    for (int np = 0; np < 2; np++) {
        const int r = wn * 32 + np * 16 + (lane & 15);
        const int c = ((lane >> 4) & 1) * 8;
        bAddr[np] = sbase + G_MTX_B + (r * GLD + c) * 2;
    }

    float acc[4][4][4];
#pragma unroll
    for (int i = 0; i < 4; i++)
#pragma unroll
        for (int j = 0; j < 4; j++)
#pragma unroll
            for (int c = 0; c < 4; c++) acc[i][j][c] = 0.f;

    // Loader: 2 matrices x 128 rows x 8 x16B chunks = 2048 ops, 8/thread
    auto load_stage = [&](int st, int chunk) {
        const int k0 = chunk * GKC;
        const unsigned stb = sbase + st * G_STG_B;
#pragma unroll
        for (int i = 0; i < 8; i++) {
            const int lin = tid + i * 256;
            const int mtx = lin >> 10;
            const int rem = lin & 1023;
            const int row = rem >> 3;
            const int ch = rem & 7;
            cp_async16(stb + mtx * G_MTX_B + (row * GLD + ch * 8) * 2,
                       (mtx ? Wp : Ap) + (size_t)row * NU + k0 + ch * 8);
        }
    };

    const int NCHUNK = NU / GKC;  // 16
    load_stage(0, 0); CP_COMMIT();
    load_stage(1, 1); CP_COMMIT();

    for (int chunk = 0; chunk < NCHUNK; chunk++) {
        const int st = chunk & 1;
        const unsigned stoff = st * G_STG_B;
        CP_WAIT1();
        __syncthreads();

#pragma unroll
        for (int ks = 0; ks < 4; ks++) {
            const unsigned koff = stoff + ks * 32;  // 16 fp16 cols
            unsigned b4[2][4];
            ldsm_x4(b4[0], bAddr[0] + koff);
            ldsm_x4(b4[1], bAddr[1] + koff);
#pragma unroll
            for (int mt = 0; mt < 4; mt++) {
                unsigned afr[4];
                ldsm_x4(afr, aAddr[mt] + koff);
#pragma unroll
                for (int np = 0; np < 2; np++) {
                    unsigned be[2] = {b4[np][0], b4[np][2]};
                    unsigned bo[2] = {b4[np][1], b4[np][3]};
                    mma_f16(acc[mt][2 * np], afr, be);
                    mma_f16(acc[mt][2 * np + 1], afr, bo);
                }
            }
        }

        __syncthreads();
        if (chunk + 2 < NCHUNK) load_stage(st, chunk + 2);
        CP_COMMIT();
    }

    // Epilogue
#pragma unroll
    for (int mt = 0; mt < 4; mt++) {
#pragma unroll
        for (int nt = 0; nt < 4; nt++) {
            const int m = rowBase + wm * 64 + mt * 16 + (lane >> 2);
            const int n = colBase + wn * 32 + nt * 8 + (lane & 3) * 2;
            const float b0 = bias[n];
            const float b1 = bias[n + 1];
            float v0x = acc[mt][nt][0] + b0, v0y = acc[mt][nt][1] + b1;
            float v1x = acc[mt][nt][2] + b0, v1y = acc[mt][nt][3] + b1;
            if (mode == 0) {
                *(float2*)&C[(size_t)m * NU + n] = make_float2(v0x, v0y);
                *(float2*)&C[(size_t)(m + 8) * NU + n] = make_float2(v1x, v1y);
            } else {
                const int h = n >> 6, d = n & 63;
#pragma unroll
                for (int rr = 0; rr < 2; rr++) {
                    const int mr = m + rr * 8;
                    const int b = mr >> 11, t = mr & 2047;
                    const size_t idx = (((size_t)(b * HH + h) * TT) + t) * DD + d;
                    float vx = rr ? v1x : v0x, vy = rr ? v1y : v0y;
                    __half2 hv = __floats2half2_rn(vx, vy);
                    *(__half2*)&H16[idx] = hv;
                }
            }
        }
    }
}

// ---------------------------------------------------------------------------
// fp16 tensor-core flash attention, 3-stage cp.async KV pipeline. (unchanged)
// Grid: (T/128, B*H). 256 threads = 8 warps; warp owns 16 query rows.
// ---------------------------------------------------------------------------
#define ATQ 128
#define AKV 64
#define SVLD 72                       // row stride fp16 (144B)
#define A_MTX_B (AKV * SVLD * 2)      // 9216 bytes per matrix (K or V)
#define A_STG_B (2 * A_MTX_B)         // 18432 per stage
#define A_NSTG 3
#define A_SMEM_TOTAL (A_NSTG * A_STG_B)  // 55296

__global__ __launch_bounds__(256) void attn_fp16()
{
    extern __shared__ __align__(128) char smA[];
    const unsigned sbase = smem_u32(smA);
    __half* smh = (__half*)smA;

    const int tid = threadIdx.x;
    const int lane = tid & 31;
    const int wid = tid >> 5;
    const int bh = blockIdx.y;
    const int q0 = blockIdx.x * ATQ;

    const size_t kvbase = (size_t)bh * TT * DD;
    const __half* Qp = g_q16 + kvbase + (size_t)q0 * DD;
    const __half* Kp = g_k16 + kvbase;
    const __half* Vp = g_v16 + kvbase;

    // ---- Stage Q (128x64 fp16) into stage-0 smem, pull frags to regs ----
    {
        const int r = tid >> 1;
        const int c = (tid & 1) * 32;
        const uint4* gq = (const uint4*)(Qp + (size_t)r * DD + c);
        uint4* dq = (uint4*)(smh + r * SVLD + c);
#pragma unroll
        for (int i = 0; i < 4; i++) dq[i] = gq[i];
    }
    __syncthreads();

    unsigned qf[4][4];
    {
        const int qrow = wid * 16 + (lane & 15);
        const int ccol = ((lane >> 4) & 1) * 8;
#pragma unroll
        for (int kk = 0; kk < 4; kk++)
            ldsm_x4(qf[kk], smem_u32(smh + qrow * SVLD + kk * 16 + ccol));
    }
    __syncthreads();

    unsigned kAddr[4];
#pragma unroll
    for (int np = 0; np < 4; np++) {
        const int r = np * 16 + (lane & 15);
        const int c = ((lane >> 4) & 1) * 8;
        kAddr[np] = sbase + (r * SVLD + c) * 2;
    }
    unsigned vAddr[4];
#pragma unroll
    for (int dp = 0; dp < 4; dp++) {
        const int r = (lane & 15);
        const int c = dp * 16 + ((lane >> 4) & 1) * 8;
        vAddr[dp] = sbase + A_MTX_B + (r * SVLD + c) * 2;
    }

    auto load_tile = [&](int st, int jt) {
        const unsigned stb = sbase + st * A_STG_B;
        const size_t goff = (size_t)jt * AKV * DD;
#pragma unroll
        for (int i = 0; i < 4; i++) {
            const int lin = tid + i * 256;
            const int mtx = lin >> 9;
            const int rem = lin & 511;
            const int row = rem >> 3;
            const int ch = rem & 7;
            cp_async16(stb + mtx * A_MTX_B + (row * SVLD + ch * 8) * 2,
                       (mtx ? Vp : Kp) + goff + row * DD + ch * 8);
        }
    };

    float o[8][4];
#pragma unroll
    for (int j = 0; j < 8; j++)
#pragma unroll
        for (int c = 0; c < 4; c++) o[j][c] = 0.f;
    float m_lo = -1e30f, m_hi = -1e30f, l_lo = 0.f, l_hi = 0.f;

    const int NT = TT / AKV;  // 32
    load_tile(0, 0); CP_COMMIT();
    load_tile(1, 1); CP_COMMIT();
    load_tile(2, 2); CP_COMMIT();

    int st = 0;
    for (int jt = 0; jt < NT; jt++) {
        const unsigned stoff = st * A_STG_B;
        CP_WAIT2();
        __syncthreads();

        // ---- S = Q K^T ----
        float s[8][4];
#pragma unroll
        for (int j = 0; j < 8; j++)
#pragma unroll
            for (int c = 0; c < 4; c++) s[j][c] = 0.f;

#pragma unroll
        for (int kk = 0; kk < 4; kk++) {
            const unsigned koff = stoff + kk * 32;
#pragma unroll
            for (int np = 0; np < 4; np++) {
                unsigned k4[4];
                ldsm_x4(k4, kAddr[np] + koff);
                unsigned bhe[2] = {k4[0], k4[2]}, bho[2] = {k4[1], k4[3]};
                mma_f16(s[2 * np], qf[kk], bhe);
                mma_f16(s[2 * np + 1], qf[kk], bho);
            }
        }

        // ---- Online softmax on fragments ----
        float tml = -1e30f, tmh = -1e30f;
#pragma unroll
        for (int j = 0; j < 8; j++) {
            tml = fmaxf(tml, fmaxf(s[j][0], s[j][1]));
            tmh = fmaxf(tmh, fmaxf(s[j][2], s[j][3]));
        }
        tml = fmaxf(tml, __shfl_xor_sync(0xffffffff, tml, 1));
        tml = fmaxf(tml, __shfl_xor_sync(0xffffffff, tml, 2));
        tmh = fmaxf(tmh, __shfl_xor_sync(0xffffffff, tmh, 1));
        tmh = fmaxf(tmh, __shfl_xor_sync(0xffffffff, tmh, 2));

        const float mnl = fmaxf(m_lo, tml);
        const float mnh = fmaxf(m_hi, tmh);
        const float al = __expf((m_lo - mnl) * 0.125f);
        const float ah = __expf((m_hi - mnh) * 0.125f);
        m_lo = mnl; m_hi = mnh;
        const float cl = mnl * 0.125f, ch = mnh * 0.125f;

        float suml = 0.f, sumh = 0.f;
#pragma unroll
        for (int j = 0; j < 8; j++) {
            float p0 = __expf(fmaf(s[j][0], 0.125f, -cl));
            float p1 = __expf(fmaf(s[j][1], 0.125f, -cl));
            float p2 = __expf(fmaf(s[j][2], 0.125f, -ch));
            float p3 = __expf(fmaf(s[j][3], 0.125f, -ch));
            s[j][0] = p0; s[j][1] = p1; s[j][2] = p2; s[j][3] = p3;
            suml += p0 + p1; sumh += p2 + p3;
        }
        suml += __shfl_xor_sync(0xffffffff, suml, 1);
        suml += __shfl_xor_sync(0xffffffff, suml, 2);
        sumh += __shfl_xor_sync(0xffffffff, sumh, 1);
        sumh += __shfl_xor_sync(0xffffffff, sumh, 2);
        l_lo = l_lo * al + suml;
        l_hi = l_hi * ah + sumh;

#pragma unroll
        for (int j = 0; j < 8; j++) {
            o[j][0] *= al; o[j][1] *= al; o[j][2] *= ah; o[j][3] *= ah;
        }

        // ---- O += P V ----
#pragma unroll
        for (int kk = 0; kk < 4; kk++) {
            unsigned pf[4];
            pf[0] = pack_h2(s[2 * kk][0], s[2 * kk][1]);
            pf[1] = pack_h2(s[2 * kk][2], s[2 * kk][3]);
            pf[2] = pack_h2(s[2 * kk + 1][0], s[2 * kk + 1][1]);
            pf[3] = pack_h2(s[2 * kk + 1][2], s[2 * kk + 1][3]);

            const unsigned roff = stoff + kk * 16 * SVLD * 2;
#pragma unroll
            for (int dp = 0; dp < 4; dp++) {
                unsigned v4[4];
                ldsm_x4t(v4, vAddr[dp] + roff);
                unsigned bhe[2] = {v4[0], v4[1]}, bho[2] = {v4[2], v4[3]};
                mma_f16(o[2 * dp], pf, bhe);
                mma_f16(o[2 * dp + 1], pf, bho);
            }
        }

        __syncthreads();
        if (jt + A_NSTG < NT) load_tile(st, jt + A_NSTG);
        CP_COMMIT();
        st = (st + 1 == A_NSTG) ? 0 : st + 1;
    }

    // ---- Epilogue: normalize, write fp16 ctx (b,t,h,d) ----
    const int b = bh >> 4;
    const int h = bh & 15;
    const float invl = 1.f / l_lo;
    const float invh = 1.f / l_hi;
    const int t_lo = q0 + wid * 16 + (lane >> 2);
    const int t_hi = t_lo + 8;

#pragma unroll
    for (int j = 0; j < 8; j++) {
        const int d = j * 8 + (lane & 3) * 2;
        {
            const size_t idx = ((size_t)(b * TT + t_lo) * HH + h) * DD + d;
            __half2 hv = __floats2half2_rn(o[j][0] * invl, o[j][1] * invl);
            *(__half2*)&g_c16[idx] = hv;
        }
        {
            const size_t idx = ((size_t)(b * TT + t_hi) * HH + h) * DD + d;
            __half2 hv = __floats2half2_rn(o[j][2] * invh, o[j][3] * invh);
            *(__half2*)&g_c16[idx] = hv;
        }
    }
}

// ---------------------------------------------------------------------------
// Launch
// ---------------------------------------------------------------------------
extern "C" void kernel_launch(void* const* d_in, const int* in_sizes, int n_in,
                              void* d_out, int out_size)
{
    const float* x  = (const float*)d_in[0];
    const float* Wq = (const float*)d_in[1];
    const float* bq = (const float*)d_in[2];
    const float* Wk = (const float*)d_in[3];
    const float* bk = (const float*)d_in[4];
    const float* Wv = (const float*)d_in[5];
    const float* bv = (const float*)d_in[6];
    const float* Wo = (const float*)d_in[7];
    const float* bo = (const float*)d_in[8];
    float* out = (float*)d_out;

    __half *x16, *w16, *q16, *k16, *v16, *c16;
    cudaGetSymbolAddress((void**)&x16, g_x16);
    cudaGetSymbolAddress((void**)&w16, g_w16);
    cudaGetSymbolAddress((void**)&q16, g_q16);
    cudaGetSymbolAddress((void**)&k16, g_k16);
    cudaGetSymbolAddress((void**)&v16, g_v16);
    cudaGetSymbolAddress((void**)&c16, g_c16);

    // Single fused conversion launch (grid-stride)
    to_half_all<<<2048, 256>>>((const float4*)x, (const float4*)Wq,
                               (const float4*)Wk, (const float4*)Wv,
                               (const float4*)Wo, (uint2*)x16, (uint2*)w16);

    cudaFuncSetAttribute(gemm_f16,
                         cudaFuncAttributeMaxDynamicSharedMemorySize,
                         G_SMEM_TOTAL);
    cudaFuncSetAttribute(attn_fp16,
                         cudaFuncAttributeMaxDynamicSharedMemorySize,
                         A_SMEM_TOTAL);

    // Fused Q/K/V projections (grid.z selects weight/bias/output)
    gemm_f16<<<dim3(NU / 128, MM / 128, 3), 256, G_SMEM_TOTAL>>>(
        x16, w16, bq, bk, bv, q16, k16, v16, nullptr, 1);

    attn_fp16<<<dim3(TT / ATQ, BB * HH), 256, A_SMEM_TOTAL>>>();

    // O-projection
    gemm_f16<<<dim3(NU / 128, MM / 128, 1), 256, G_SMEM_TOTAL>>>(
        c16, w16 + 3 * (size_t)NU * NU, bo, nullptr, nullptr,
        nullptr, nullptr, nullptr, out, 0);
}